// round 1
// baseline (speedup 1.0000x reference)
#include <cuda_runtime.h>
#include <cstdint>

#define DIM 256
#define MATSZ (DIM*DIM)
#define NPOS 2048

// ---------------- device scratch (static: no allocation allowed) -------------
__device__ float g_eA[2*MATSZ];      // A = (prim^T - prim) / 64  (so expm(A)^64 = expm(S^T) = M)
__device__ float g_bufP[2*MATSZ];    // ping
__device__ float g_bufQ[2*MATSZ];    // pong
__device__ float g_mats[2*MATSZ];    // M[0], M[1]
__device__ float g_tabs[510*MATSZ];  // tables T_k, k=1..8; T_k[c] at offset ((1<<k)-2 + c)

// ---------------- 64x64-tile fp32 matmul core --------------------------------
// Block: 256 threads (16x16 logical). Each thread computes a 4x4 micro-tile.
// C[tm..tm+64)[tn..tn+64) = alpha * A*B (+ I if addI)
__device__ __forceinline__ void mm_tile(const float* __restrict__ A,
                                        const float* __restrict__ B,
                                        float* __restrict__ C,
                                        float alpha, int addI)
{
    __shared__ float As[16][64];   // As[k][row]
    __shared__ float Bs[16][64];   // Bs[k][col]
    const int tid = threadIdx.x;
    const int tx  = tid & 15;
    const int ty  = tid >> 4;
    const int tm  = blockIdx.y * 64;
    const int tn  = blockIdx.x * 64;

    const int arow = tid >> 2;         // 0..63
    const int akc  = (tid & 3) << 2;   // 0,4,8,12

    float acc[4][4];
    #pragma unroll
    for (int i = 0; i < 4; i++)
        #pragma unroll
        for (int j = 0; j < 4; j++) acc[i][j] = 0.0f;

    for (int k0 = 0; k0 < DIM; k0 += 16) {
        float4 a4 = *(const float4*)(A + (size_t)(tm + arow)*DIM + k0 + akc);
        As[akc+0][arow] = a4.x;
        As[akc+1][arow] = a4.y;
        As[akc+2][arow] = a4.z;
        As[akc+3][arow] = a4.w;
        float4 b4 = *(const float4*)(B + (size_t)(k0 + ty)*DIM + tn + tx*4);
        *(float4*)(&Bs[ty][tx*4]) = b4;
        __syncthreads();
        #pragma unroll
        for (int kk = 0; kk < 16; kk++) {
            float4 a = *(const float4*)(&As[kk][ty*4]);
            float4 b = *(const float4*)(&Bs[kk][tx*4]);
            acc[0][0] += a.x*b.x; acc[0][1] += a.x*b.y; acc[0][2] += a.x*b.z; acc[0][3] += a.x*b.w;
            acc[1][0] += a.y*b.x; acc[1][1] += a.y*b.y; acc[1][2] += a.y*b.z; acc[1][3] += a.y*b.w;
            acc[2][0] += a.z*b.x; acc[2][1] += a.z*b.y; acc[2][2] += a.z*b.z; acc[2][3] += a.z*b.w;
            acc[3][0] += a.w*b.x; acc[3][1] += a.w*b.y; acc[3][2] += a.w*b.z; acc[3][3] += a.w*b.w;
        }
        __syncthreads();
    }
    #pragma unroll
    for (int i = 0; i < 4; i++) {
        const int gr = tm + ty*4 + i;
        #pragma unroll
        for (int j = 0; j < 4; j++) {
            const int gc = tn + tx*4 + j;
            float v = alpha * acc[i][j];
            if (addI && gr == gc) v += 1.0f;
            C[(size_t)gr*DIM + gc] = v;
        }
    }
}

__device__ __forceinline__ void tile_copy(const float* __restrict__ S, float* __restrict__ C)
{
    const int tm = blockIdx.y * 64, tn = blockIdx.x * 64;
    const int r0 = threadIdx.x >> 4;
    const int c0 = (threadIdx.x & 15) * 4;
    #pragma unroll
    for (int r = 0; r < 4; r++) {
        const int row = tm + r0 + r*16;
        const int col = tn + c0;
        *(float4*)(C + (size_t)row*DIM + col) = *(const float4*)(S + (size_t)row*DIM + col);
    }
}

__device__ __forceinline__ void tile_ident(float* __restrict__ C)
{
    const int tm = blockIdx.y * 64, tn = blockIdx.x * 64;
    const int r0 = threadIdx.x >> 4;
    const int c0 = (threadIdx.x & 15) * 4;
    #pragma unroll
    for (int r = 0; r < 4; r++) {
        const int row = tm + r0 + r*16;
        const int col = tn + c0;
        float4 v;
        v.x = (row == col+0) ? 1.0f : 0.0f;
        v.y = (row == col+1) ? 1.0f : 0.0f;
        v.z = (row == col+2) ? 1.0f : 0.0f;
        v.w = (row == col+3) ? 1.0f : 0.0f;
        *(float4*)(C + (size_t)row*DIM + col) = v;
    }
}

// ---------------- kernels -----------------------------------------------------

// A = (prim^T - prim)/64 ; bufP = I + A/12 (Horner init, Taylor degree 12)
__global__ void k_skew(const float* __restrict__ prim)
{
    const int idx = blockIdx.x * blockDim.x + threadIdx.x;   // 0 .. 2*MATSZ-1
    if (idx >= 2*MATSZ) return;
    const int b  = idx >> 16;
    const int ij = idx & 65535;
    const int i  = ij >> 8, j = ij & 255;
    const float v = (prim[(size_t)b*MATSZ + (size_t)j*DIM + i] -
                     prim[(size_t)b*MATSZ + (size_t)i*DIM + j]) * (1.0f/64.0f);
    g_eA[idx]  = v;
    g_bufP[idx] = v * (1.0f/12.0f) + ((i == j) ? 1.0f : 0.0f);
}

// batched (z dim) C = alpha*A*B (+I)
__global__ void k_mm_batch(const float* __restrict__ A, const float* __restrict__ B,
                           float* __restrict__ C, float alpha, int addI)
{
    const size_t off = (size_t)blockIdx.z * MATSZ;
    mm_tile(A + off, B + off, C + off, alpha, addI);
}

// level-1 tables: T_1[b] = M[b]
__global__ void k_tab1()
{
    const size_t off = (size_t)blockIdx.z * MATSZ;
    tile_copy(g_mats + off, g_tabs + off);
}

// level-i tables (i>=2): T_i[c] = T_{i-1}[c & (2^{i-1}-1)] * M[c >> (i-1)]
__global__ void k_tab(int lvl)
{
    const int c = blockIdx.z;
    const int lowbits = lvl - 1;
    const int lowmask = (1 << lowbits) - 1;
    const float* A = g_tabs + (size_t)(((1 << lowbits) - 2) + (c & lowmask)) * MATSZ;
    const float* B = g_mats + (size_t)(c >> lowbits) * MATSZ;
    float*       C = g_tabs + (size_t)(((1 << lvl) - 2) + c) * MATSZ;
    mm_tile(A, B, C, 1.0f, 0);
}

// leaf: out[n] = T8[p&255] * T_{len-8}[(p>>8)&mask]   (or table copy / identity)
__global__ void k_leaf(const int* __restrict__ unique, float* __restrict__ out)
{
    const int n = blockIdx.z;
    const unsigned p = (unsigned)unique[n];
    const int len = 31 - __clz((int)p);       // p >= 1 guaranteed
    float* C = out + (size_t)n * MATSZ;
    if (len == 0) {
        tile_ident(C);
    } else if (len <= 8) {
        const float* S = g_tabs + (size_t)(((1u << len) - 2u) + (p & ((1u << len) - 1u))) * MATSZ;
        tile_copy(S, C);
    } else {
        const int hi = len - 8;
        const float* A = g_tabs + (size_t)(254u + (p & 255u)) * MATSZ;
        const float* B = g_tabs + (size_t)(((1u << hi) - 2u) + ((p >> 8) & ((1u << hi) - 1u))) * MATSZ;
        mm_tile(A, B, C, 1.0f, 0);
    }
}

// ---------------- host orchestration -----------------------------------------
extern "C" void kernel_launch(void* const* d_in, const int* in_sizes, int n_in,
                              void* d_out, int out_size)
{
    const float* prim   = (const float*)d_in[0];
    const int*   unique = (const int*)d_in[2];
    float*       out    = (float*)d_out;
    (void)in_sizes; (void)n_in; (void)out_size;

    float *pA, *pP, *pQ, *pM;
    cudaGetSymbolAddress((void**)&pA, g_eA);
    cudaGetSymbolAddress((void**)&pP, g_bufP);
    cudaGetSymbolAddress((void**)&pQ, g_bufQ);
    cudaGetSymbolAddress((void**)&pM, g_mats);

    const dim3 mmBlk(256);
    const dim3 mm2(4, 4, 2);

    // 1) A = (prim^T - prim)/64 ; T = I + A/12
    k_skew<<<(2*MATSZ + 255)/256, 256>>>(prim);

    // 2) Horner: for k=11..1: T <- I + (A*T)/k      (11 matmuls, batched over b)
    float* cur = pP;
    float* nxt = pQ;
    for (int k = 11; k >= 1; --k) {
        k_mm_batch<<<mm2, mmBlk>>>(pA, cur, nxt, 1.0f/(float)k, 1);
        float* t = cur; cur = nxt; nxt = t;
    }
    // 3) 6 squarings (2^6 scaling); last one lands in g_mats
    for (int s = 0; s < 6; ++s) {
        float* dst = (s == 5) ? pM : nxt;
        k_mm_batch<<<mm2, mmBlk>>>(cur, cur, dst, 1.0f, 0);
        float* t = cur; cur = dst; nxt = t;
    }

    // 4) tables: T_1 = M ; T_i built from T_{i-1}
    k_tab1<<<dim3(4,4,2), mmBlk>>>();
    for (int lvl = 2; lvl <= 8; ++lvl) {
        k_tab<<<dim3(4, 4, 1 << lvl), mmBlk>>>(lvl);
    }

    // 5) leaves: one matmul (or copy) per position
    k_leaf<<<dim3(4, 4, NPOS), mmBlk>>>(unique, out);
}

// round 3
// speedup vs baseline: 2.2628x; 2.2628x over previous
#include <cuda_runtime.h>
#include <cuda_bf16.h>
#include <cstdint>

#define DIM 256
#define MATSZ (DIM*DIM)
#define NPOS 2048
#define ROWH 40                        // padded row length (bf16 elems) = 80B
#define ROWB (ROWH*2)                  // 80 bytes
#define TILE_BYTES (128*ROWB)          // 10240
#define STAGE_BYTES (4*TILE_BYTES)     // Ahi, Alo, Bhi, Blo
#define SMEM_BYTES (2*STAGE_BYTES)     // 81920

// ---------------- static device scratch --------------------------------------
__device__ float g_eA  [2*MATSZ];
__device__ float g_bufP[2*MATSZ];
__device__ float g_bufPT[2*MATSZ];
__device__ float g_bufQ[2*MATSZ];
__device__ float g_bufQT[2*MATSZ];
__device__ float g_mats [2*MATSZ];
__device__ float g_matsT[2*MATSZ];
__device__ float g_tabs [510*MATSZ];   // T_k row-major, offset (1<<k)-2+c
__device__ float g_tabsT[510*MATSZ];   // transposed copies (B operands)

// ---------------- helpers -----------------------------------------------------
__device__ __forceinline__ uint32_t smem_u32(const void* p) {
    uint32_t a;
    asm("{ .reg .u64 t; cvta.to.shared.u64 t, %1; cvt.u32.u64 %0, t; }" : "=r"(a) : "l"(p));
    return a;
}
__device__ __forceinline__ void ldm4(uint32_t a[4], uint32_t addr) {
    asm volatile("ldmatrix.sync.aligned.m8n8.x4.shared.b16 {%0,%1,%2,%3}, [%4];"
                 : "=r"(a[0]), "=r"(a[1]), "=r"(a[2]), "=r"(a[3]) : "r"(addr));
}
__device__ __forceinline__ void mma16816(float c[4], const uint32_t a[4],
                                         uint32_t b0, uint32_t b1) {
    asm volatile("mma.sync.aligned.m16n8k16.row.col.f32.bf16.bf16.f32 "
                 "{%0,%1,%2,%3}, {%4,%5,%6,%7}, {%8,%9}, {%0,%1,%2,%3};"
                 : "+f"(c[0]), "+f"(c[1]), "+f"(c[2]), "+f"(c[3])
                 : "r"(a[0]), "r"(a[1]), "r"(a[2]), "r"(a[3]), "r"(b0), "r"(b1));
}

// ---------------- GEMM core: C[128x128 tile] = alpha*X*Y (+I) ------------------
// X row-major [256,256] (rows mo..mo+127); Yt row-major holds Y^T (rows no..no+127).
// 3xBF16 split accumulation in fp32. Optionally writes Ct = C^T.
__device__ __forceinline__ void gemm_tile(const float* __restrict__ X,
                                          const float* __restrict__ Yt,
                                          float* __restrict__ C,
                                          float* __restrict__ Ct,
                                          float alpha, int addI, int mo, int no)
{
    extern __shared__ char sm[];
    const uint32_t smb = smem_u32(sm);
    const int tid = threadIdx.x, lane = tid & 31, wid = tid >> 5;
    const int m0w = (wid & 3) * 32;
    const int n0w = (wid >> 2) * 64;

    // global load mapping: 2 threads per row, 16 floats each
    const int lr  = tid >> 1;
    const int lkh = (tid & 1) << 4;
    const float* gA = X  + (size_t)(mo + lr) * DIM + lkh;
    const float* gB = Yt + (size_t)(no + lr) * DIM + lkh;
    const uint32_t stRow = (uint32_t)lr * ROWB + (uint32_t)lkh * 2;

    float acc[2][8][4];
    #pragma unroll
    for (int mt = 0; mt < 2; ++mt)
        #pragma unroll
        for (int nb = 0; nb < 8; ++nb)
            #pragma unroll
            for (int q = 0; q < 4; ++q) acc[mt][nb][q] = 0.0f;

    float4 pa[4], pb[4];
    #pragma unroll
    for (int j = 0; j < 4; ++j) {
        pa[j] = *(const float4*)(gA + j * 4);
        pb[j] = *(const float4*)(gB + j * 4);
    }

    auto storeStage = [&](int sidx) {
        char* base = sm + sidx * STAGE_BYTES;
        #pragma unroll
        for (int j = 0; j < 4; ++j) {
            const uint32_t off = stRow + j * 8;
            {
                float4 v = pa[j];
                __nv_bfloat16 hx = __float2bfloat16(v.x), hy = __float2bfloat16(v.y);
                __nv_bfloat16 hz = __float2bfloat16(v.z), hw = __float2bfloat16(v.w);
                __nv_bfloat16 lx = __float2bfloat16(v.x - __bfloat162float(hx));
                __nv_bfloat16 ly = __float2bfloat16(v.y - __bfloat162float(hy));
                __nv_bfloat16 lz = __float2bfloat16(v.z - __bfloat162float(hz));
                __nv_bfloat16 lw = __float2bfloat16(v.w - __bfloat162float(hw));
                *(__nv_bfloat162*)(base + off)                  = __halves2bfloat162(hx, hy);
                *(__nv_bfloat162*)(base + off + 4)              = __halves2bfloat162(hz, hw);
                *(__nv_bfloat162*)(base + TILE_BYTES + off)     = __halves2bfloat162(lx, ly);
                *(__nv_bfloat162*)(base + TILE_BYTES + off + 4) = __halves2bfloat162(lz, lw);
            }
            {
                float4 v = pb[j];
                __nv_bfloat16 hx = __float2bfloat16(v.x), hy = __float2bfloat16(v.y);
                __nv_bfloat16 hz = __float2bfloat16(v.z), hw = __float2bfloat16(v.w);
                __nv_bfloat16 lx = __float2bfloat16(v.x - __bfloat162float(hx));
                __nv_bfloat16 ly = __float2bfloat16(v.y - __bfloat162float(hy));
                __nv_bfloat16 lz = __float2bfloat16(v.z - __bfloat162float(hz));
                __nv_bfloat16 lw = __float2bfloat16(v.w - __bfloat162float(hw));
                *(__nv_bfloat162*)(base + 2*TILE_BYTES + off)     = __halves2bfloat162(hx, hy);
                *(__nv_bfloat162*)(base + 2*TILE_BYTES + off + 4) = __halves2bfloat162(hz, hw);
                *(__nv_bfloat162*)(base + 3*TILE_BYTES + off)     = __halves2bfloat162(lx, ly);
                *(__nv_bfloat162*)(base + 3*TILE_BYTES + off + 4) = __halves2bfloat162(lz, lw);
            }
        }
    };

    storeStage(0);
    __syncthreads();

    // per-lane ldmatrix byte offsets
    const uint32_t aRow = (uint32_t)(m0w + (lane & 15)) * ROWB + ((lane & 16) ? 16u : 0u);
    const uint32_t bRow = (uint32_t)(n0w + (lane & 7) + ((lane & 16) ? 8 : 0)) * ROWB
                          + ((lane & 8) ? 16u : 0u);

    for (int c = 0; c < 8; ++c) {
        const uint32_t stg = smb + (uint32_t)(c & 1) * STAGE_BYTES;
        if (c < 7) {
            const float* ga = gA + (c + 1) * 32;
            const float* gb = gB + (c + 1) * 32;
            #pragma unroll
            for (int j = 0; j < 4; ++j) {
                pa[j] = *(const float4*)(ga + j * 4);
                pb[j] = *(const float4*)(gb + j * 4);
            }
        }
        #pragma unroll
        for (int pass = 0; pass < 3; ++pass) {
            const uint32_t aBase = stg + (pass == 2 ? TILE_BYTES : 0u);
            const uint32_t bBase = stg + 2u*TILE_BYTES + (pass == 1 ? TILE_BYTES : 0u);
            #pragma unroll
            for (int s = 0; s < 2; ++s) {
                uint32_t af[2][4];
                ldm4(af[0], aBase + aRow + s * 32);
                ldm4(af[1], aBase + aRow + s * 32 + 16u * ROWB);
                uint32_t bf[4][4];
                #pragma unroll
                for (int nt = 0; nt < 4; ++nt)
                    ldm4(bf[nt], bBase + bRow + s * 32 + (uint32_t)nt * 16u * ROWB);
                #pragma unroll
                for (int mt = 0; mt < 2; ++mt)
                    #pragma unroll
                    for (int nb = 0; nb < 8; ++nb)
                        mma16816(acc[mt][nb], af[mt], bf[nb >> 1][(nb & 1) * 2],
                                 bf[nb >> 1][(nb & 1) * 2 + 1]);
            }
        }
        if (c < 7) storeStage((c + 1) & 1);
        __syncthreads();
    }

    // epilogue
    const int r0 = lane >> 2;
    const int cp = (lane & 3) * 2;
    #pragma unroll
    for (int mt = 0; mt < 2; ++mt) {
        const int gr0 = mo + m0w + mt * 16 + r0;
        const int gr1 = gr0 + 8;
        #pragma unroll
        for (int nb = 0; nb < 8; ++nb) {
            const int gc = no + n0w + nb * 8 + cp;
            float v0 = alpha * acc[mt][nb][0];
            float v1 = alpha * acc[mt][nb][1];
            float v2 = alpha * acc[mt][nb][2];
            float v3 = alpha * acc[mt][nb][3];
            if (addI) {
                if (gr0 == gc)     v0 += 1.0f;
                if (gr0 == gc + 1) v1 += 1.0f;
                if (gr1 == gc)     v2 += 1.0f;
                if (gr1 == gc + 1) v3 += 1.0f;
            }
            *(float2*)(C + (size_t)gr0 * DIM + gc) = make_float2(v0, v1);
            *(float2*)(C + (size_t)gr1 * DIM + gc) = make_float2(v2, v3);
            if (Ct) {
                Ct[(size_t)gc * DIM + gr0]       = v0;
                Ct[(size_t)(gc + 1) * DIM + gr0] = v1;
                Ct[(size_t)gc * DIM + gr1]       = v2;
                Ct[(size_t)(gc + 1) * DIM + gr1] = v3;
            }
        }
    }
}

// ---------------- kernels -----------------------------------------------------

// A = (prim^T - prim)/8 ; seed T = I + A/6 (Taylor d=6, s=3 squarings)
__global__ void k_skew(const float* __restrict__ prim)
{
    int idx = blockIdx.x * blockDim.x + threadIdx.x;
    if (idx >= 2 * MATSZ) return;
    int b = idx >> 16, ij = idx & 65535, i = ij >> 8, j = ij & 255;
    float a = (prim[(size_t)b * MATSZ + (size_t)j * DIM + i] -
               prim[(size_t)b * MATSZ + (size_t)i * DIM + j]) * 0.125f;
    g_eA[idx] = a;
    float d = (i == j) ? 1.0f : 0.0f;
    g_bufP [idx] = d + a * (1.0f / 6.0f);
    g_bufPT[idx] = d - a * (1.0f / 6.0f);
}

__global__ __launch_bounds__(256, 1)
void k_gemm(const float* X, const float* Yt, float* C, float* Ct,
            float alpha, int addI)
{
    const size_t off = (size_t)blockIdx.z * MATSZ;
    gemm_tile(X + off, Yt + off, C + off, Ct + off, alpha, addI,
              blockIdx.y * 128, blockIdx.x * 128);
}

__global__ void k_copy1()
{
    int idx = blockIdx.x * blockDim.x + threadIdx.x;
    if (idx < 2 * MATSZ) {
        g_tabs [idx] = g_mats [idx];
        g_tabsT[idx] = g_matsT[idx];
    }
}

__global__ __launch_bounds__(256, 1)
void k_tab(int lvl)
{
    const int c = blockIdx.z;
    const int lb = lvl - 1;
    const float* X  = g_tabs  + (size_t)(((1 << lb) - 2) + (c & ((1 << lb) - 1))) * MATSZ;
    const float* Yt = g_matsT + (size_t)(c >> lb) * MATSZ;
    float* Co = g_tabs  + (size_t)(((1 << lvl) - 2) + c) * MATSZ;
    float* Ct = g_tabsT + (size_t)(((1 << lvl) - 2) + c) * MATSZ;
    gemm_tile(X, Yt, Co, Ct, 1.0f, 0, blockIdx.y * 128, blockIdx.x * 128);
}

__global__ __launch_bounds__(256, 1)
void k_leaf(const int* __restrict__ unique, float* __restrict__ out)
{
    const int n = blockIdx.z;
    const unsigned p = (unsigned)unique[n];
    const int len = 31 - __clz((int)p);
    float* C = out + (size_t)n * MATSZ;
    const int mo = blockIdx.y * 128;
    const int no = blockIdx.x * 128;
    if (len >= 9) {
        const float* X = g_tabs + (size_t)(254u + (p & 255u)) * MATSZ;
        const int hb = len - 8;
        const float* Yt = g_tabsT +
            (size_t)(((1u << hb) - 2u) + ((p >> 8) & ((1u << hb) - 1u))) * MATSZ;
        gemm_tile(X, Yt, C, nullptr, 1.0f, 0, mo, no);
    } else if (len >= 1) {
        const float* S = g_tabs +
            (size_t)(((1u << len) - 2u) + (p & ((1u << len) - 1u))) * MATSZ;
        for (int i = threadIdx.x; i < 128 * 32; i += 256) {
            int r = mo + (i >> 5), c4 = no + (i & 31) * 4;
            *(float4*)(C + (size_t)r * DIM + c4) = *(const float4*)(S + (size_t)r * DIM + c4);
        }
    } else {
        for (int i = threadIdx.x; i < 128 * 32; i += 256) {
            int r = mo + (i >> 5), c4 = no + (i & 31) * 4;
            float4 w;
            w.x = (r == c4 + 0) ? 1.0f : 0.0f;
            w.y = (r == c4 + 1) ? 1.0f : 0.0f;
            w.z = (r == c4 + 2) ? 1.0f : 0.0f;
            w.w = (r == c4 + 3) ? 1.0f : 0.0f;
            *(float4*)(C + (size_t)r * DIM + c4) = w;
        }
    }
}

// ---------------- host orchestration -----------------------------------------
extern "C" void kernel_launch(void* const* d_in, const int* in_sizes, int n_in,
                              void* d_out, int out_size)
{
    const float* prim   = (const float*)d_in[0];
    const int*   unique = (const int*)d_in[2];
    float*       out    = (float*)d_out;
    (void)in_sizes; (void)n_in; (void)out_size;

    cudaFuncSetAttribute(k_gemm, cudaFuncAttributeMaxDynamicSharedMemorySize, SMEM_BYTES);
    cudaFuncSetAttribute(k_tab,  cudaFuncAttributeMaxDynamicSharedMemorySize, SMEM_BYTES);
    cudaFuncSetAttribute(k_leaf, cudaFuncAttributeMaxDynamicSharedMemorySize, SMEM_BYTES);

    float *pA, *pP, *pPT, *pQ, *pQT, *pM, *pMT;
    cudaGetSymbolAddress((void**)&pA,  g_eA);
    cudaGetSymbolAddress((void**)&pP,  g_bufP);
    cudaGetSymbolAddress((void**)&pPT, g_bufPT);
    cudaGetSymbolAddress((void**)&pQ,  g_bufQ);
    cudaGetSymbolAddress((void**)&pQT, g_bufQT);
    cudaGetSymbolAddress((void**)&pM,  g_mats);
    cudaGetSymbolAddress((void**)&pMT, g_matsT);

    // 1) skew + Horner seed
    k_skew<<<(2 * MATSZ + 255) / 256, 256>>>(prim);

    // 2) Horner k=5..1: T <- I + (A*T)/k   (batch 2)
    float *cur = pP, *curT = pPT, *nxt = pQ, *nxtT = pQT;
    for (int k = 5; k >= 1; --k) {
        k_gemm<<<dim3(2, 2, 2), 256, SMEM_BYTES>>>(pA, curT, nxt, nxtT, 1.0f / (float)k, 1);
        float* t;
        t = cur;  cur  = nxt;  nxt  = t;
        t = curT; curT = nxtT; nxtT = t;
    }
    // 3) 3 squarings; last lands in g_mats/g_matsT
    for (int sq = 0; sq < 3; ++sq) {
        float* dC  = (sq == 2) ? pM  : nxt;
        float* dCT = (sq == 2) ? pMT : nxtT;
        k_gemm<<<dim3(2, 2, 2), 256, SMEM_BYTES>>>(cur, curT, dC, dCT, 1.0f, 0);
        nxt = cur;  nxtT = curT;
        cur = dC;   curT = dCT;
    }

    // 4) tables
    k_copy1<<<(2 * MATSZ + 255) / 256, 256>>>();
    for (int lvl = 2; lvl <= 8; ++lvl)
        k_tab<<<dim3(2, 2, 1 << lvl), 256, SMEM_BYTES>>>(lvl);

    // 5) leaves
    k_leaf<<<dim3(2, 2, NPOS), 256, SMEM_BYTES>>>(unique, out);
}

// round 4
// speedup vs baseline: 2.3093x; 1.0206x over previous
#include <cuda_runtime.h>
#include <cuda_bf16.h>
#include <cstdint>

#define DIM 256
#define MATSZ (DIM*DIM)
#define NPOS 2048
#define DEPTH 4
#define TILEB 8192            // 128 rows * 64 B (32 bf16)
#define STAGEB (4*TILEB)      // Ahi, Alo, Bhi, Blo = 32 KB
#define SMEMB (DEPTH*STAGEB)  // 128 KB

using bf16 = __nv_bfloat16;

// ---------------- static device scratch --------------------------------------
__device__ bf16 g_eAh[2*MATSZ], g_eAl[2*MATSZ];          // A operand splits (row-major)
__device__ bf16 g_TAh[2][2*MATSZ], g_TAl[2][2*MATSZ];    // expm ping-pong, A-layout
__device__ bf16 g_TBh[2][2*MATSZ], g_TBl[2][2*MATSZ];    // expm ping-pong, B-layout
__device__ bf16 g_tabAh[510*MATSZ], g_tabAl[510*MATSZ];  // tables, A-layout (row-major)
__device__ bf16 g_tabBh[510*MATSZ], g_tabBl[510*MATSZ];  // tables, B-layout (transposed)

// ---------------- helpers -----------------------------------------------------
__device__ __forceinline__ uint32_t smem_u32(const void* p) {
    uint32_t a;
    asm("{ .reg .u64 t; cvta.to.shared.u64 t, %1; cvt.u32.u64 %0, t; }" : "=r"(a) : "l"(p));
    return a;
}
__device__ __forceinline__ void ldm4(uint32_t a[4], uint32_t addr) {
    asm volatile("ldmatrix.sync.aligned.m8n8.x4.shared.b16 {%0,%1,%2,%3}, [%4];"
                 : "=r"(a[0]), "=r"(a[1]), "=r"(a[2]), "=r"(a[3]) : "r"(addr));
}
__device__ __forceinline__ void mma16816(float c[4], const uint32_t a[4],
                                         uint32_t b0, uint32_t b1) {
    asm volatile("mma.sync.aligned.m16n8k16.row.col.f32.bf16.bf16.f32 "
                 "{%0,%1,%2,%3}, {%4,%5,%6,%7}, {%8,%9}, {%0,%1,%2,%3};"
                 : "+f"(c[0]), "+f"(c[1]), "+f"(c[2]), "+f"(c[3])
                 : "r"(a[0]), "r"(a[1]), "r"(a[2]), "r"(a[3]), "r"(b0), "r"(b1));
}
__device__ __forceinline__ void cp16(uint32_t s, const void* g) {
    asm volatile("cp.async.cg.shared.global [%0], [%1], 16;" :: "r"(s), "l"(g));
}
__device__ __forceinline__ void cp_commit() {
    asm volatile("cp.async.commit_group;" ::: "memory");
}
__device__ __forceinline__ void cp_wait2() {
    asm volatile("cp.async.wait_group 2;" ::: "memory");
}
// swizzle: 64B rows, 4x16B chunks; chunk' = chunk ^ ((row>>1)&3)
__device__ __forceinline__ uint32_t swz(uint32_t row, uint32_t byteInRow) {
    uint32_t chunk = byteInRow >> 4;
    return row * 64u + ((chunk ^ ((row >> 1) & 3u)) << 4) + (byteInRow & 15u);
}

// ---------------- GEMM core ---------------------------------------------------
// C[mo:mo+128, no:no+128] = alpha * A*B (+I), A/B given as bf16 hi/lo splits.
// A arrays row-major [256][256] (rows=m,k); B arrays row-major of B^T (rows=n,k).
// Outputs: fp32 outF and/or split layouts (A-layout oAh/oAl, B-layout oBh/oBl).
__device__ __forceinline__ void gemm_core(
    const bf16* __restrict__ Ah, const bf16* __restrict__ Al,
    const bf16* __restrict__ Bh, const bf16* __restrict__ Bl,
    float* __restrict__ outF, bf16* __restrict__ oAh, bf16* __restrict__ oAl,
    bf16* __restrict__ oBh, bf16* __restrict__ oBl, float alpha, int addI)
{
    extern __shared__ char sm[];
    const uint32_t smb = smem_u32(sm);
    const int tid = threadIdx.x, lane = tid & 31, wid = tid >> 5;
    const int mo = blockIdx.y * 128, no = blockIdx.x * 128;
    const int m0w = (wid & 3) * 32, n0w = (wid >> 2) * 64;

    // cp.async mapping: thread -> row lr, two 16B chunks
    const int lr  = tid >> 1;
    const int lc0 = (tid & 1) * 2;
    const bf16* gAh = Ah + (size_t)(mo + lr) * DIM;
    const bf16* gAl = Al + (size_t)(mo + lr) * DIM;
    const bf16* gBh = Bh + (size_t)(no + lr) * DIM;
    const bf16* gBl = Bl + (size_t)(no + lr) * DIM;

    float acc[2][8][4];
    #pragma unroll
    for (int mt = 0; mt < 2; ++mt)
        #pragma unroll
        for (int nb = 0; nb < 8; ++nb)
            #pragma unroll
            for (int q = 0; q < 4; ++q) acc[mt][nb][q] = 0.0f;

    auto issue = [&](int c) {
        const uint32_t st = smb + (uint32_t)(c & (DEPTH - 1)) * STAGEB;
        #pragma unroll
        for (int q = 0; q < 2; ++q) {
            const uint32_t cc = (uint32_t)(lc0 + q);
            const uint32_t sd = st + swz((uint32_t)lr, cc * 16u);
            const int ge = c * 32 + (int)cc * 8;
            cp16(sd,             gAh + ge);
            cp16(sd + TILEB,     gAl + ge);
            cp16(sd + 2*TILEB,   gBh + ge);
            cp16(sd + 3*TILEB,   gBl + ge);
        }
    };

    #pragma unroll
    for (int p = 0; p < DEPTH - 1; ++p) { issue(p); cp_commit(); }

    for (int c = 0; c < 8; ++c) {
        cp_wait2();
        __syncthreads();
        if (c + DEPTH - 1 < 8) issue(c + DEPTH - 1);
        cp_commit();

        const uint32_t st = smb + (uint32_t)(c & (DEPTH - 1)) * STAGEB;
        #pragma unroll
        for (int s = 0; s < 2; ++s) {
            uint32_t ah[2][4], al[2][4], bh[4][4], bl[4][4];
            #pragma unroll
            for (int mt = 0; mt < 2; ++mt) {
                const uint32_t row  = (uint32_t)(m0w + mt * 16 + (lane & 15));
                const uint32_t byte = (uint32_t)(s * 32 + ((lane & 16) ? 16 : 0));
                const uint32_t ad = st + swz(row, byte);
                ldm4(ah[mt], ad);
                ldm4(al[mt], ad + TILEB);
            }
            #pragma unroll
            for (int nt = 0; nt < 4; ++nt) {
                const uint32_t row  = (uint32_t)(n0w + nt * 16 + (lane & 7) + ((lane & 16) ? 8 : 0));
                const uint32_t byte = (uint32_t)(s * 32 + ((lane & 8) ? 16 : 0));
                const uint32_t bd = st + 2u * TILEB + swz(row, byte);
                ldm4(bh[nt], bd);
                ldm4(bl[nt], bd + TILEB);
            }
            #pragma unroll
            for (int mt = 0; mt < 2; ++mt)
                #pragma unroll
                for (int nb = 0; nb < 8; ++nb) {
                    const uint32_t b0h = bh[nb >> 1][(nb & 1) * 2];
                    const uint32_t b1h = bh[nb >> 1][(nb & 1) * 2 + 1];
                    const uint32_t b0l = bl[nb >> 1][(nb & 1) * 2];
                    const uint32_t b1l = bl[nb >> 1][(nb & 1) * 2 + 1];
                    mma16816(acc[mt][nb], ah[mt], b0h, b1h);
                    mma16816(acc[mt][nb], ah[mt], b0l, b1l);
                    mma16816(acc[mt][nb], al[mt], b0h, b1h);
                }
        }
    }

    // ---------------- epilogue ----------------
    const int r0 = lane >> 2, cq = (lane & 3) * 2;
    #pragma unroll
    for (int mt = 0; mt < 2; ++mt) {
        #pragma unroll
        for (int half = 0; half < 2; ++half) {
            const int gr = mo + m0w + mt * 16 + r0 + half * 8;
            #pragma unroll
            for (int nb = 0; nb < 8; ++nb) {
                const int gc = no + n0w + nb * 8 + cq;
                float v0 = alpha * acc[mt][nb][half * 2 + 0];
                float v1 = alpha * acc[mt][nb][half * 2 + 1];
                if (addI) {
                    if (gr == gc)     v0 += 1.0f;
                    if (gr == gc + 1) v1 += 1.0f;
                }
                if (outF)
                    *(float2*)(outF + (size_t)gr * DIM + gc) = make_float2(v0, v1);
                if (oBh) {
                    bf16 h0 = __float2bfloat16(v0), h1 = __float2bfloat16(v1);
                    bf16 l0 = __float2bfloat16(v0 - __bfloat162float(h0));
                    bf16 l1 = __float2bfloat16(v1 - __bfloat162float(h1));
                    oBh[(size_t)gc * DIM + gr]       = h0;
                    oBh[(size_t)(gc + 1) * DIM + gr] = h1;
                    oBl[(size_t)gc * DIM + gr]       = l0;
                    oBl[(size_t)(gc + 1) * DIM + gr] = l1;
                    if (oAh) {
                        *(__nv_bfloat162*)(oAh + (size_t)gr * DIM + gc) = __halves2bfloat162(h0, h1);
                        *(__nv_bfloat162*)(oAl + (size_t)gr * DIM + gc) = __halves2bfloat162(l0, l1);
                    }
                }
            }
        }
    }
}

// ---------------- kernels -----------------------------------------------------

// a_ij = A[i][j] = (prim[j][i]-prim[i][j])/8; seed T0 = I + A/6 stored B-layout.
__global__ void k_skew(const float* __restrict__ prim, bf16* TBh, bf16* TBl)
{
    int idx = blockIdx.x * blockDim.x + threadIdx.x;
    if (idx >= 2 * MATSZ) return;
    int b = idx >> 16, ij = idx & 65535, i = ij >> 8, j = ij & 255;
    float a = (prim[(size_t)b * MATSZ + (size_t)j * DIM + i] -
               prim[(size_t)b * MATSZ + (size_t)i * DIM + j]) * 0.125f;
    bf16 h = __float2bfloat16(a);
    g_eAh[idx] = h;
    g_eAl[idx] = __float2bfloat16(a - __bfloat162float(h));
    float d = (i == j) ? 1.0f : 0.0f;
    float tb = d - a * (1.0f / 6.0f);        // T0^T[i][j]
    bf16 th = __float2bfloat16(tb);
    TBh[idx] = th;
    TBl[idx] = __float2bfloat16(tb - __bfloat162float(th));
}

__global__ __launch_bounds__(256, 1)
void k_gemm_split(const bf16* Ah, const bf16* Al, const bf16* Bh, const bf16* Bl,
                  bf16* oAh, bf16* oAl, bf16* oBh, bf16* oBl, float alpha, int addI)
{
    const size_t off = (size_t)blockIdx.z * MATSZ;
    gemm_core(Ah + off, Al + off, Bh + off, Bl + off, nullptr,
              oAh ? oAh + off : nullptr, oAl ? oAl + off : nullptr,
              oBh + off, oBl + off, alpha, addI);
}

__global__ __launch_bounds__(256, 1)
void k_tab(int lvl)
{
    const int c = blockIdx.z;
    const int lb = lvl - 1;
    const size_t aoff = (size_t)(((1 << lb) - 2) + (c & ((1 << lb) - 1))) * MATSZ;
    const size_t boff = (size_t)(c >> lb) * MATSZ;          // level-1 slots = M[b]
    const size_t ooff = (size_t)(((1 << lvl) - 2) + c) * MATSZ;
    gemm_core(g_tabAh + aoff, g_tabAl + aoff, g_tabBh + boff, g_tabBl + boff,
              nullptr, g_tabAh + ooff, g_tabAl + ooff, g_tabBh + ooff, g_tabBl + ooff,
              1.0f, 0);
}

__global__ __launch_bounds__(256, 1)
void k_leaf(const int* __restrict__ unique, float* __restrict__ out)
{
    const int n = blockIdx.z;
    const unsigned p = (unsigned)unique[n];
    const int len = 31 - __clz((int)p);
    float* C = out + (size_t)n * MATSZ;
    const int mo = blockIdx.y * 128, no = blockIdx.x * 128;
    if (len >= 9) {
        const size_t aoff = (size_t)(254u + (p & 255u)) * MATSZ;
        const int hb = len - 8;
        const size_t boff = (size_t)(((1u << hb) - 2u) + ((p >> 8) & ((1u << hb) - 1u))) * MATSZ;
        gemm_core(g_tabAh + aoff, g_tabAl + aoff, g_tabBh + boff, g_tabBl + boff,
                  C, nullptr, nullptr, nullptr, nullptr, 1.0f, 0);
    } else if (len >= 1) {
        const size_t s = (size_t)(((1u << len) - 2u) + (p & ((1u << len) - 1u))) * MATSZ;
        for (int i = threadIdx.x; i < 128 * 64; i += 256) {
            const int r = mo + (i >> 6), c2 = no + (i & 63) * 2;
            const size_t e = s + (size_t)r * DIM + c2;
            __nv_bfloat162 h = *(const __nv_bfloat162*)(g_tabAh + e);
            __nv_bfloat162 l = *(const __nv_bfloat162*)(g_tabAl + e);
            *(float2*)(C + (size_t)r * DIM + c2) =
                make_float2(__bfloat162float(h.x) + __bfloat162float(l.x),
                            __bfloat162float(h.y) + __bfloat162float(l.y));
        }
    } else {
        for (int i = threadIdx.x; i < 128 * 32; i += 256) {
            const int r = mo + (i >> 5), c4 = no + (i & 31) * 4;
            float4 w;
            w.x = (r == c4 + 0) ? 1.0f : 0.0f;
            w.y = (r == c4 + 1) ? 1.0f : 0.0f;
            w.z = (r == c4 + 2) ? 1.0f : 0.0f;
            w.w = (r == c4 + 3) ? 1.0f : 0.0f;
            *(float4*)(C + (size_t)r * DIM + c4) = w;
        }
    }
}

// ---------------- host orchestration -----------------------------------------
extern "C" void kernel_launch(void* const* d_in, const int* in_sizes, int n_in,
                              void* d_out, int out_size)
{
    const float* prim   = (const float*)d_in[0];
    const int*   unique = (const int*)d_in[2];
    float*       out    = (float*)d_out;
    (void)in_sizes; (void)n_in; (void)out_size;

    cudaFuncSetAttribute(k_gemm_split, cudaFuncAttributeMaxDynamicSharedMemorySize, SMEMB);
    cudaFuncSetAttribute(k_tab,  cudaFuncAttributeMaxDynamicSharedMemorySize, SMEMB);
    cudaFuncSetAttribute(k_leaf, cudaFuncAttributeMaxDynamicSharedMemorySize, SMEMB);

    bf16 *eAh, *eAl, *TAh, *TAl, *TBh, *TBl, *tAh, *tAl, *tBh, *tBl;
    cudaGetSymbolAddress((void**)&eAh, g_eAh);
    cudaGetSymbolAddress((void**)&eAl, g_eAl);
    cudaGetSymbolAddress((void**)&TAh, g_TAh);
    cudaGetSymbolAddress((void**)&TAl, g_TAl);
    cudaGetSymbolAddress((void**)&TBh, g_TBh);
    cudaGetSymbolAddress((void**)&TBl, g_TBl);
    cudaGetSymbolAddress((void**)&tAh, g_tabAh);
    cudaGetSymbolAddress((void**)&tAl, g_tabAl);
    cudaGetSymbolAddress((void**)&tBh, g_tabBh);
    cudaGetSymbolAddress((void**)&tBl, g_tabBl);

    auto TA_h = [&](int i) { return TAh + (size_t)i * 2 * MATSZ; };
    auto TA_l = [&](int i) { return TAl + (size_t)i * 2 * MATSZ; };
    auto TB_h = [&](int i) { return TBh + (size_t)i * 2 * MATSZ; };
    auto TB_l = [&](int i) { return TBl + (size_t)i * 2 * MATSZ; };

    const dim3 g222(2, 2, 2), blk(256);

    // 1) skew + seed (ping = buffer 0, B-layout)
    k_skew<<<(2 * MATSZ + 255) / 256, 256>>>(prim, TB_h(0), TB_l(0));

    // 2) Horner k=5..1: T <- I + (A*T)/k.  Last round also writes A-layout.
    int cur = 0;
    for (int k = 5; k >= 1; --k) {
        const int nxt = cur ^ 1;
        const bool last = (k == 1);
        k_gemm_split<<<g222, blk, SMEMB>>>(
            eAh, eAl, TB_h(cur), TB_l(cur),
            last ? TA_h(nxt) : nullptr, last ? TA_l(nxt) : nullptr,
            TB_h(nxt), TB_l(nxt), 1.0f / (float)k, 1);
        cur = nxt;
    }
    // 3) squarings x3: S <- S*S. Last writes straight into table level-1 slots.
    for (int sq = 0; sq < 3; ++sq) {
        const int nxt = cur ^ 1;
        const bool last = (sq == 2);
        k_gemm_split<<<g222, blk, SMEMB>>>(
            TA_h(cur), TA_l(cur), TB_h(cur), TB_l(cur),
            last ? tAh : TA_h(nxt), last ? tAl : TA_l(nxt),
            last ? tBh : TB_h(nxt), last ? tBl : TB_l(nxt), 1.0f, 0);
        cur = nxt;
    }

    // 4) tables levels 2..8
    for (int lvl = 2; lvl <= 8; ++lvl)
        k_tab<<<dim3(2, 2, 1 << lvl), blk, SMEMB>>>(lvl);

    // 5) leaves
    k_leaf<<<dim3(2, 2, NPOS), blk, SMEMB>>>(unique, out);
}

// round 5
// speedup vs baseline: 2.3123x; 1.0013x over previous
#include <cuda_runtime.h>
#include <cuda_bf16.h>
#include <cstdint>

#define DIM 256
#define MATSZ (DIM*DIM)
#define NPOS 2048
#define NITEMS (NPOS*4)
#define PGRID 148
#define DEPTH 4
#define TILEB 8192              // 128 rows * 64B (32 bf16)
#define STAGEB (4*TILEB)        // Ahi,Alo,Bhi,Blo = 32KB
#define STAGESB (DEPTH*STAGEB)  // 128KB
#define SMEM_DYN (STAGESB + 2048)
#define PITCH 129

using bf16 = __nv_bfloat16;

// ---------------- static device scratch --------------------------------------
__device__ bf16 g_eAh[2*MATSZ], g_eAl[2*MATSZ];
__device__ bf16 g_TAh[2][2*MATSZ], g_TAl[2][2*MATSZ];
__device__ bf16 g_TBh[2][2*MATSZ], g_TBl[2][2*MATSZ];
__device__ bf16 g_tabAh[510*MATSZ], g_tabAl[510*MATSZ];
__device__ bf16 g_tabBh[510*MATSZ], g_tabBl[510*MATSZ];

// ---------------- helpers -----------------------------------------------------
__device__ __forceinline__ uint32_t smem_u32(const void* p) {
    uint32_t a;
    asm("{ .reg .u64 t; cvta.to.shared.u64 t, %1; cvt.u32.u64 %0, t; }" : "=r"(a) : "l"(p));
    return a;
}
__device__ __forceinline__ void ldm4(uint32_t a[4], uint32_t addr) {
    asm volatile("ldmatrix.sync.aligned.m8n8.x4.shared.b16 {%0,%1,%2,%3}, [%4];"
                 : "=r"(a[0]), "=r"(a[1]), "=r"(a[2]), "=r"(a[3]) : "r"(addr));
}
__device__ __forceinline__ void mma16816(float c[4], const uint32_t a[4],
                                         uint32_t b0, uint32_t b1) {
    asm volatile("mma.sync.aligned.m16n8k16.row.col.f32.bf16.bf16.f32 "
                 "{%0,%1,%2,%3}, {%4,%5,%6,%7}, {%8,%9}, {%0,%1,%2,%3};"
                 : "+f"(c[0]), "+f"(c[1]), "+f"(c[2]), "+f"(c[3])
                 : "r"(a[0]), "r"(a[1]), "r"(a[2]), "r"(a[3]), "r"(b0), "r"(b1));
}
__device__ __forceinline__ void cp16(uint32_t s, const void* g) {
    asm volatile("cp.async.cg.shared.global [%0], [%1], 16;" :: "r"(s), "l"(g));
}
__device__ __forceinline__ void cp_commit() {
    asm volatile("cp.async.commit_group;" ::: "memory");
}
__device__ __forceinline__ void cp_wait2() {
    asm volatile("cp.async.wait_group 2;" ::: "memory");
}
__device__ __forceinline__ uint32_t swz(uint32_t row, uint32_t byteInRow) {
    uint32_t chunk = byteInRow >> 4;
    return row * 64u + ((chunk ^ ((row >> 1) & 3u)) << 4) + (byteInRow & 15u);
}

// ---------------- compute one k32 chunk (16 warps, warp tile 32x32) -----------
__device__ __forceinline__ void mma_chunk(uint32_t st, int lane, int m0w, int n0w,
                                          float acc[2][4][4])
{
    #pragma unroll
    for (int s = 0; s < 2; ++s) {
        uint32_t ah[2][4], al[2][4], bh[2][4], bl[2][4];
        #pragma unroll
        for (int mt = 0; mt < 2; ++mt) {
            const uint32_t ad = st + swz((uint32_t)(m0w + mt * 16 + (lane & 15)),
                                         (uint32_t)(s * 32 + ((lane & 16) ? 16 : 0)));
            ldm4(ah[mt], ad);
            ldm4(al[mt], ad + TILEB);
        }
        #pragma unroll
        for (int nt = 0; nt < 2; ++nt) {
            const uint32_t bd = st + 2u * TILEB +
                swz((uint32_t)(n0w + nt * 16 + (lane & 7) + ((lane & 16) ? 8 : 0)),
                    (uint32_t)(s * 32 + ((lane & 8) ? 16 : 0)));
            ldm4(bh[nt], bd);
            ldm4(bl[nt], bd + TILEB);
        }
        #pragma unroll
        for (int mt = 0; mt < 2; ++mt)
            #pragma unroll
            for (int nb = 0; nb < 4; ++nb) {
                const uint32_t b0h = bh[nb >> 1][(nb & 1) * 2];
                const uint32_t b1h = bh[nb >> 1][(nb & 1) * 2 + 1];
                const uint32_t b0l = bl[nb >> 1][(nb & 1) * 2];
                const uint32_t b1l = bl[nb >> 1][(nb & 1) * 2 + 1];
                mma16816(acc[mt][nb], ah[mt], b0h, b1h);
                mma16816(acc[mt][nb], ah[mt], b0l, b1l);
                mma16816(acc[mt][nb], al[mt], b0h, b1h);
            }
    }
}

// ---------------- single-tile GEMM (expm / tables) ----------------------------
__device__ __forceinline__ void gemm8(const bf16* __restrict__ Ah, const bf16* __restrict__ Al,
                                      const bf16* __restrict__ Bh, const bf16* __restrict__ Bl,
                                      int mo, int no, float acc[2][4][4])
{
    extern __shared__ char sm[];
    const uint32_t smb = smem_u32(sm);
    const int tid = threadIdx.x, lane = tid & 31, wid = tid >> 5;
    const int m0w = (wid & 3) * 32, n0w = (wid >> 2) * 32;
    const int lr = tid >> 2, cc = tid & 3;

    const bf16* gAh = Ah + (size_t)(mo + lr) * DIM + cc * 8;
    const bf16* gAl = Al + (size_t)(mo + lr) * DIM + cc * 8;
    const bf16* gBh = Bh + (size_t)(no + lr) * DIM + cc * 8;
    const bf16* gBl = Bl + (size_t)(no + lr) * DIM + cc * 8;
    const uint32_t sd0 = swz((uint32_t)lr, (uint32_t)cc * 16u);

    #pragma unroll
    for (int mt = 0; mt < 2; ++mt)
        #pragma unroll
        for (int nb = 0; nb < 4; ++nb)
            #pragma unroll
            for (int q = 0; q < 4; ++q) acc[mt][nb][q] = 0.0f;

    auto issue = [&](int c) {
        const uint32_t st = smb + (uint32_t)(c & (DEPTH - 1)) * STAGEB;
        const int ge = c * 32;
        cp16(st + sd0,             gAh + ge);
        cp16(st + sd0 + TILEB,     gAl + ge);
        cp16(st + sd0 + 2*TILEB,   gBh + ge);
        cp16(st + sd0 + 3*TILEB,   gBl + ge);
    };

    #pragma unroll
    for (int p = 0; p < DEPTH - 1; ++p) { issue(p); cp_commit(); }

    for (int c = 0; c < 8; ++c) {
        cp_wait2();
        __syncthreads();
        if (c + DEPTH - 1 < 8) issue(c + DEPTH - 1);
        cp_commit();
        mma_chunk(smb + (uint32_t)(c & (DEPTH - 1)) * STAGEB, lane, m0w, n0w, acc);
    }
}

// ---------------- staged split epilogue (expm / tables) -----------------------
__device__ __forceinline__ void epi_split(float acc[2][4][4], float alpha, int addI,
                                          int mo, int no,
                                          bf16* __restrict__ oAh, bf16* __restrict__ oAl,
                                          bf16* __restrict__ oBh, bf16* __restrict__ oBl)
{
    extern __shared__ char sm[];
    float* sf = (float*)sm;
    const int tid = threadIdx.x, lane = tid & 31, wid = tid >> 5;
    const int m0w = (wid & 3) * 32, n0w = (wid >> 2) * 32;
    const int r0 = lane >> 2, cq = (lane & 3) * 2;

    __syncthreads();   // stage buffers free
    #pragma unroll
    for (int mt = 0; mt < 2; ++mt)
        #pragma unroll
        for (int half = 0; half < 2; ++half) {
            const int row = m0w + mt * 16 + r0 + half * 8;
            const int gr = mo + row;
            #pragma unroll
            for (int nb = 0; nb < 4; ++nb) {
                const int col = n0w + nb * 8 + cq;
                const int gc = no + col;
                float v0 = alpha * acc[mt][nb][half * 2 + 0];
                float v1 = alpha * acc[mt][nb][half * 2 + 1];
                if (addI) {
                    if (gr == gc)     v0 += 1.0f;
                    if (gr == gc + 1) v1 += 1.0f;
                }
                sf[row * PITCH + col]     = v0;
                sf[row * PITCH + col + 1] = v1;
            }
        }
    __syncthreads();

    // A-layout (row-major) coalesced
    if (oAh) {
        const int r = tid & 127, cg = tid >> 7;
        const int c0 = cg * 32;
        uint32_t hv[16], lv[16];
        #pragma unroll
        for (int j = 0; j < 16; ++j) {
            float f0 = sf[r * PITCH + c0 + 2*j];
            float f1 = sf[r * PITCH + c0 + 2*j + 1];
            bf16 h0 = __float2bfloat16(f0), h1 = __float2bfloat16(f1);
            bf16 l0 = __float2bfloat16(f0 - __bfloat162float(h0));
            bf16 l1 = __float2bfloat16(f1 - __bfloat162float(h1));
            __nv_bfloat162 hh = __halves2bfloat162(h0, h1);
            __nv_bfloat162 ll = __halves2bfloat162(l0, l1);
            hv[j] = *(uint32_t*)&hh;
            lv[j] = *(uint32_t*)&ll;
        }
        uint4* dh = (uint4*)(oAh + (size_t)(mo + r) * DIM + no + c0);
        uint4* dl = (uint4*)(oAl + (size_t)(mo + r) * DIM + no + c0);
        #pragma unroll
        for (int q = 0; q < 4; ++q) {
            dh[q] = make_uint4(hv[4*q], hv[4*q+1], hv[4*q+2], hv[4*q+3]);
            dl[q] = make_uint4(lv[4*q], lv[4*q+1], lv[4*q+2], lv[4*q+3]);
        }
    }
    // B-layout (transposed, row-major of C^T) coalesced
    {
        const int c = tid & 127, rg = tid >> 7;
        const int rb = rg * 32;
        uint32_t hv[16], lv[16];
        #pragma unroll
        for (int j = 0; j < 16; ++j) {
            float f0 = sf[(rb + 2*j)     * PITCH + c];
            float f1 = sf[(rb + 2*j + 1) * PITCH + c];
            bf16 h0 = __float2bfloat16(f0), h1 = __float2bfloat16(f1);
            bf16 l0 = __float2bfloat16(f0 - __bfloat162float(h0));
            bf16 l1 = __float2bfloat16(f1 - __bfloat162float(h1));
            __nv_bfloat162 hh = __halves2bfloat162(h0, h1);
            __nv_bfloat162 ll = __halves2bfloat162(l0, l1);
            hv[j] = *(uint32_t*)&hh;
            lv[j] = *(uint32_t*)&ll;
        }
        uint4* dh = (uint4*)(oBh + (size_t)(no + c) * DIM + mo + rb);
        uint4* dl = (uint4*)(oBl + (size_t)(no + c) * DIM + mo + rb);
        #pragma unroll
        for (int q = 0; q < 4; ++q) {
            dh[q] = make_uint4(hv[4*q], hv[4*q+1], hv[4*q+2], hv[4*q+3]);
            dl[q] = make_uint4(lv[4*q], lv[4*q+1], lv[4*q+2], lv[4*q+3]);
        }
    }
    __syncthreads();
}

// ---------------- kernels -----------------------------------------------------
__global__ void k_skew(const float* __restrict__ prim, bf16* TBh, bf16* TBl)
{
    int idx = blockIdx.x * blockDim.x + threadIdx.x;
    if (idx >= 2 * MATSZ) return;
    int b = idx >> 16, ij = idx & 65535, i = ij >> 8, j = ij & 255;
    float a = (prim[(size_t)b * MATSZ + (size_t)j * DIM + i] -
               prim[(size_t)b * MATSZ + (size_t)i * DIM + j]) * 0.125f;
    bf16 h = __float2bfloat16(a);
    g_eAh[idx] = h;
    g_eAl[idx] = __float2bfloat16(a - __bfloat162float(h));
    float d = (i == j) ? 1.0f : 0.0f;
    float tb = d - a * (1.0f / 6.0f);
    bf16 th = __float2bfloat16(tb);
    TBh[idx] = th;
    TBl[idx] = __float2bfloat16(tb - __bfloat162float(th));
}

__global__ __launch_bounds__(512, 1)
void k_gemm_split(const bf16* Ah, const bf16* Al, const bf16* Bh, const bf16* Bl,
                  bf16* oAh, bf16* oAl, bf16* oBh, bf16* oBl, float alpha, int addI)
{
    const size_t off = (size_t)blockIdx.z * MATSZ;
    const int mo = blockIdx.y * 128, no = blockIdx.x * 128;
    float acc[2][4][4];
    gemm8(Ah + off, Al + off, Bh + off, Bl + off, mo, no, acc);
    epi_split(acc, alpha, addI, mo, no,
              oAh ? oAh + off : nullptr, oAl ? oAl + off : nullptr,
              oBh + off, oBl + off);
}

__global__ __launch_bounds__(512, 1)
void k_tab(int lvl)
{
    const int c = blockIdx.z;
    const int lb = lvl - 1;
    const size_t aoff = (size_t)(((1 << lb) - 2) + (c & ((1 << lb) - 1))) * MATSZ;
    const size_t boff = (size_t)(c >> lb) * MATSZ;
    const size_t ooff = (size_t)(((1 << lvl) - 2) + c) * MATSZ;
    const int mo = blockIdx.y * 128, no = blockIdx.x * 128;
    float acc[2][4][4];
    gemm8(g_tabAh + aoff, g_tabAl + aoff, g_tabBh + boff, g_tabBl + boff, mo, no, acc);
    epi_split(acc, 1.0f, 0, mo, no,
              g_tabAh + ooff, g_tabAl + ooff, g_tabBh + ooff, g_tabBl + ooff);
}

// ---------------- persistent leaf kernel --------------------------------------
__global__ __launch_bounds__(512, 1)
void k_leaf(const int* __restrict__ unique, float* __restrict__ out)
{
    extern __shared__ char sm[];
    const uint32_t smb = smem_u32(sm);
    uint4* metaM = (uint4*)(sm + STAGESB);
    uint4* metaC = metaM + 60;
    __shared__ int cntM, cntC;
    const int tid = threadIdx.x, lane = tid & 31, wid = tid >> 5;
    const int m0w = (wid & 3) * 32, n0w = (wid >> 2) * 32;
    const int bid = blockIdx.x;

    if (tid == 0) { cntM = 0; cntC = 0; }
    __syncthreads();

    // build item lists
    {
        const int w = bid + tid * PGRID;
        if (w < NITEMS) {
            const int n = w >> 2, tile = w & 3;
            const unsigned p = (unsigned)unique[n];
            const int len = 31 - __clz((int)p);
            if (len >= 9) {
                const uint32_t aIdx = 254u + (p & 255u);
                const int hb = len - 8;
                const uint32_t bIdx = ((1u << hb) - 2u) + ((p >> 8) & ((1u << hb) - 1u));
                const int s = atomicAdd(&cntM, 1);
                metaM[s] = make_uint4(aIdx, bIdx, (uint32_t)((n << 2) | tile), 0);
            } else {
                const uint32_t sIdx = (len >= 1)
                    ? (((1u << len) - 2u) + (p & ((1u << len) - 1u))) : 0xFFFFFFFFu;
                const int s = atomicAdd(&cntC, 1);
                metaC[s] = make_uint4(sIdx, 0, (uint32_t)((n << 2) | tile), 0);
            }
        }
    }
    __syncthreads();

    // ---- copy / identity items ----
    for (int i = 0; i < cntC; ++i) {
        const uint4 mt4 = metaC[i];
        const int n = (int)(mt4.z >> 2), tile = (int)(mt4.z & 3);
        const int mo = (tile >> 1) * 128, no = (tile & 1) * 128;
        float* C = out + (size_t)n * MATSZ;
        const int r = tid >> 2, cb = (tid & 3) * 32;
        if (mt4.x != 0xFFFFFFFFu) {
            const bf16* sh = g_tabAh + (size_t)mt4.x * MATSZ + (size_t)(mo + r) * DIM + no + cb;
            const bf16* sl = g_tabAl + (size_t)mt4.x * MATSZ + (size_t)(mo + r) * DIM + no + cb;
            float* d = C + (size_t)(mo + r) * DIM + no + cb;
            #pragma unroll
            for (int j = 0; j < 16; ++j) {
                __nv_bfloat162 h = *(const __nv_bfloat162*)(sh + 2*j);
                __nv_bfloat162 l = *(const __nv_bfloat162*)(sl + 2*j);
                *(float2*)(d + 2*j) =
                    make_float2(__bfloat162float(h.x) + __bfloat162float(l.x),
                                __bfloat162float(h.y) + __bfloat162float(l.y));
            }
        } else {
            float* d = C + (size_t)(mo + r) * DIM + no + cb;
            #pragma unroll
            for (int j = 0; j < 32; ++j)
                d[j] = ((mo + r) == (no + cb + j)) ? 1.0f : 0.0f;
        }
    }

    // ---- mma items: one continuous pipeline ----
    const int G = cntM * 8;
    if (G == 0) return;
    const int lr = tid >> 2, cc = tid & 3;
    const uint32_t sd0 = swz((uint32_t)lr, (uint32_t)cc * 16u);
    const size_t rowOffA = (size_t)lr * DIM + cc * 8;

    auto issue = [&](int g) {
        const uint4 mt4 = metaM[g >> 3];
        const int c = g & 7, tile = (int)(mt4.z & 3);
        const int mo = (tile >> 1) * 128, no = (tile & 1) * 128;
        const uint32_t st = smb + (uint32_t)(g & (DEPTH - 1)) * STAGEB;
        const size_t ao = (size_t)mt4.x * MATSZ + (size_t)mo * DIM + rowOffA + c * 32;
        const size_t bo = (size_t)mt4.y * MATSZ + (size_t)no * DIM + rowOffA + c * 32;
        cp16(st + sd0,           g_tabAh + ao);
        cp16(st + sd0 + TILEB,   g_tabAl + ao);
        cp16(st + sd0 + 2*TILEB, g_tabBh + bo);
        cp16(st + sd0 + 3*TILEB, g_tabBl + bo);
    };

    float acc[2][4][4];
    #pragma unroll
    for (int mt = 0; mt < 2; ++mt)
        #pragma unroll
        for (int nb = 0; nb < 4; ++nb)
            #pragma unroll
            for (int q = 0; q < 4; ++q) acc[mt][nb][q] = 0.0f;

    #pragma unroll
    for (int p = 0; p < DEPTH - 1; ++p) {
        if (p < G) issue(p);
        cp_commit();
    }

    for (int g = 0; g < G; ++g) {
        cp_wait2();
        __syncthreads();
        if (g + DEPTH - 1 < G) issue(g + DEPTH - 1);
        cp_commit();
        mma_chunk(smb + (uint32_t)(g & (DEPTH - 1)) * STAGEB, lane, m0w, n0w, acc);

        if ((g & 7) == 7) {
            const uint4 mt4 = metaM[g >> 3];
            const int n = (int)(mt4.z >> 2), tile = (int)(mt4.z & 3);
            const int mo = (tile >> 1) * 128, no = (tile & 1) * 128;
            float* C = out + (size_t)n * MATSZ;
            const int r0 = lane >> 2, cq = (lane & 3) * 2;
            #pragma unroll
            for (int mt = 0; mt < 2; ++mt)
                #pragma unroll
                for (int half = 0; half < 2; ++half) {
                    const int gr = mo + m0w + mt * 16 + r0 + half * 8;
                    #pragma unroll
                    for (int nb = 0; nb < 4; ++nb) {
                        const int gc = no + n0w + nb * 8 + cq;
                        *(float2*)(C + (size_t)gr * DIM + gc) =
                            make_float2(acc[mt][nb][half * 2], acc[mt][nb][half * 2 + 1]);
                        acc[mt][nb][half * 2] = 0.0f;
                        acc[mt][nb][half * 2 + 1] = 0.0f;
                    }
                }
        }
    }
}

// ---------------- host orchestration -----------------------------------------
extern "C" void kernel_launch(void* const* d_in, const int* in_sizes, int n_in,
                              void* d_out, int out_size)
{
    const float* prim   = (const float*)d_in[0];
    const int*   unique = (const int*)d_in[2];
    float*       out    = (float*)d_out;
    (void)in_sizes; (void)n_in; (void)out_size;

    cudaFuncSetAttribute(k_gemm_split, cudaFuncAttributeMaxDynamicSharedMemorySize, SMEM_DYN);
    cudaFuncSetAttribute(k_tab,  cudaFuncAttributeMaxDynamicSharedMemorySize, SMEM_DYN);
    cudaFuncSetAttribute(k_leaf, cudaFuncAttributeMaxDynamicSharedMemorySize, SMEM_DYN);

    bf16 *eAh, *eAl, *TAh, *TAl, *TBh, *TBl, *tAh, *tAl, *tBh, *tBl;
    cudaGetSymbolAddress((void**)&eAh, g_eAh);
    cudaGetSymbolAddress((void**)&eAl, g_eAl);
    cudaGetSymbolAddress((void**)&TAh, g_TAh);
    cudaGetSymbolAddress((void**)&TAl, g_TAl);
    cudaGetSymbolAddress((void**)&TBh, g_TBh);
    cudaGetSymbolAddress((void**)&TBl, g_TBl);
    cudaGetSymbolAddress((void**)&tAh, g_tabAh);
    cudaGetSymbolAddress((void**)&tAl, g_tabAl);
    cudaGetSymbolAddress((void**)&tBh, g_tabBh);
    cudaGetSymbolAddress((void**)&tBl, g_tabBl);

    auto TA_h = [&](int i) { return TAh + (size_t)i * 2 * MATSZ; };
    auto TA_l = [&](int i) { return TAl + (size_t)i * 2 * MATSZ; };
    auto TB_h = [&](int i) { return TBh + (size_t)i * 2 * MATSZ; };
    auto TB_l = [&](int i) { return TBl + (size_t)i * 2 * MATSZ; };

    const dim3 g222(2, 2, 2), blk(512);

    k_skew<<<(2 * MATSZ + 255) / 256, 256>>>(prim, TB_h(0), TB_l(0));

    int cur = 0;
    for (int k = 5; k >= 1; --k) {
        const int nxt = cur ^ 1;
        const bool last = (k == 1);
        k_gemm_split<<<g222, blk, SMEM_DYN>>>(
            eAh, eAl, TB_h(cur), TB_l(cur),
            last ? TA_h(nxt) : nullptr, last ? TA_l(nxt) : nullptr,
            TB_h(nxt), TB_l(nxt), 1.0f / (float)k, 1);
        cur = nxt;
    }
    for (int sq = 0; sq < 3; ++sq) {
        const int nxt = cur ^ 1;
        const bool last = (sq == 2);
        k_gemm_split<<<g222, blk, SMEM_DYN>>>(
            TA_h(cur), TA_l(cur), TB_h(cur), TB_l(cur),
            last ? tAh : TA_h(nxt), last ? tAl : TA_l(nxt),
            last ? tBh : TB_h(nxt), last ? tBl : TB_l(nxt), 1.0f, 0);
        cur = nxt;
    }

    for (int lvl = 2; lvl <= 8; ++lvl)
        k_tab<<<dim3(2, 2, 1 << lvl), blk, SMEM_DYN>>>(lvl);

    k_leaf<<<PGRID, blk, SMEM_DYN>>>(unique, out);
}

// round 6
// speedup vs baseline: 3.7366x; 1.6160x over previous
#include <cuda_runtime.h>
#include <cuda_fp16.h>
#include <cstdint>

#define DIM 256
#define MATSZ (DIM*DIM)
#define NPOS 2048
#define NITEMS (NPOS*4)
#define PGRID 148
#define DEPTH 4
#define TILEB 8192              // 128 rows * 64B (32 fp16)
#define STAGEB (4*TILEB)        // Ahi,Alo,Bhi,Blo = 32KB (tables/expm)
#define LSTAGEB (2*TILEB)       // Ahi,Bhi = 16KB (leaf)
#define STAGESB (DEPTH*STAGEB)  // 128KB
#define SMEM_DYN (STAGESB + 2048)
#define PITCH 129

using f16 = __half;

// ---------------- static device scratch --------------------------------------
__device__ f16 g_eAh[2*MATSZ], g_eAl[2*MATSZ];
__device__ f16 g_TAh[2][2*MATSZ], g_TAl[2][2*MATSZ];
__device__ f16 g_TBh[2][2*MATSZ], g_TBl[2][2*MATSZ];
__device__ f16 g_tabAh[510*MATSZ], g_tabAl[510*MATSZ];
__device__ f16 g_tabBh[510*MATSZ], g_tabBl[510*MATSZ];

// ---------------- helpers -----------------------------------------------------
__device__ __forceinline__ uint32_t smem_u32(const void* p) {
    uint32_t a;
    asm("{ .reg .u64 t; cvta.to.shared.u64 t, %1; cvt.u32.u64 %0, t; }" : "=r"(a) : "l"(p));
    return a;
}
__device__ __forceinline__ void ldm4(uint32_t a[4], uint32_t addr) {
    asm volatile("ldmatrix.sync.aligned.m8n8.x4.shared.b16 {%0,%1,%2,%3}, [%4];"
                 : "=r"(a[0]), "=r"(a[1]), "=r"(a[2]), "=r"(a[3]) : "r"(addr));
}
__device__ __forceinline__ void mma16816(float c[4], const uint32_t a[4],
                                         uint32_t b0, uint32_t b1) {
    asm volatile("mma.sync.aligned.m16n8k16.row.col.f32.f16.f16.f32 "
                 "{%0,%1,%2,%3}, {%4,%5,%6,%7}, {%8,%9}, {%0,%1,%2,%3};"
                 : "+f"(c[0]), "+f"(c[1]), "+f"(c[2]), "+f"(c[3])
                 : "r"(a[0]), "r"(a[1]), "r"(a[2]), "r"(a[3]), "r"(b0), "r"(b1));
}
__device__ __forceinline__ void cp16(uint32_t s, const void* g) {
    asm volatile("cp.async.cg.shared.global [%0], [%1], 16;" :: "r"(s), "l"(g));
}
__device__ __forceinline__ void cp_commit() {
    asm volatile("cp.async.commit_group;" ::: "memory");
}
__device__ __forceinline__ void cp_wait2() {
    asm volatile("cp.async.wait_group 2;" ::: "memory");
}
__device__ __forceinline__ uint32_t swz(uint32_t row, uint32_t byteInRow) {
    uint32_t chunk = byteInRow >> 4;
    return row * 64u + ((chunk ^ ((row >> 1) & 3u)) << 4) + (byteInRow & 15u);
}
__device__ __forceinline__ uint32_t pack_hi(float f0, float f1, uint32_t& lo) {
    f16 h0 = __float2half(f0), h1 = __float2half(f1);
    f16 l0 = __float2half(f0 - __half2float(h0));
    f16 l1 = __float2half(f1 - __half2float(h1));
    __half2 hh = __halves2half2(h0, h1);
    __half2 ll = __halves2half2(l0, l1);
    lo = *(uint32_t*)&ll;
    return *(uint32_t*)&hh;
}

// ---------------- 3-product chunk (tables / expm) -----------------------------
__device__ __forceinline__ void mma_chunk3(uint32_t st, int lane, int m0w, int n0w,
                                           float acc[2][4][4])
{
    #pragma unroll
    for (int s = 0; s < 2; ++s) {
        uint32_t ah[2][4], al[2][4], bh[2][4], bl[2][4];
        #pragma unroll
        for (int mt = 0; mt < 2; ++mt) {
            const uint32_t ad = st + swz((uint32_t)(m0w + mt * 16 + (lane & 15)),
                                         (uint32_t)(s * 32 + ((lane & 16) ? 16 : 0)));
            ldm4(ah[mt], ad);
            ldm4(al[mt], ad + TILEB);
        }
        #pragma unroll
        for (int nt = 0; nt < 2; ++nt) {
            const uint32_t bd = st + 2u * TILEB +
                swz((uint32_t)(n0w + nt * 16 + (lane & 7) + ((lane & 16) ? 8 : 0)),
                    (uint32_t)(s * 32 + ((lane & 8) ? 16 : 0)));
            ldm4(bh[nt], bd);
            ldm4(bl[nt], bd + TILEB);
        }
        #pragma unroll
        for (int mt = 0; mt < 2; ++mt)
            #pragma unroll
            for (int nb = 0; nb < 4; ++nb) {
                const uint32_t b0h = bh[nb >> 1][(nb & 1) * 2];
                const uint32_t b1h = bh[nb >> 1][(nb & 1) * 2 + 1];
                const uint32_t b0l = bl[nb >> 1][(nb & 1) * 2];
                const uint32_t b1l = bl[nb >> 1][(nb & 1) * 2 + 1];
                mma16816(acc[mt][nb], ah[mt], b0h, b1h);
                mma16816(acc[mt][nb], ah[mt], b0l, b1l);
                mma16816(acc[mt][nb], al[mt], b0h, b1h);
            }
    }
}

// ---------------- 1-product chunk (leaf) --------------------------------------
__device__ __forceinline__ void mma_chunk1(uint32_t st, int lane, int m0w, int n0w,
                                           float acc[2][4][4])
{
    #pragma unroll
    for (int s = 0; s < 2; ++s) {
        uint32_t ah[2][4], bh[2][4];
        #pragma unroll
        for (int mt = 0; mt < 2; ++mt)
            ldm4(ah[mt], st + swz((uint32_t)(m0w + mt * 16 + (lane & 15)),
                                  (uint32_t)(s * 32 + ((lane & 16) ? 16 : 0))));
        #pragma unroll
        for (int nt = 0; nt < 2; ++nt)
            ldm4(bh[nt], st + TILEB +
                 swz((uint32_t)(n0w + nt * 16 + (lane & 7) + ((lane & 16) ? 8 : 0)),
                     (uint32_t)(s * 32 + ((lane & 8) ? 16 : 0))));
        #pragma unroll
        for (int mt = 0; mt < 2; ++mt)
            #pragma unroll
            for (int nb = 0; nb < 4; ++nb)
                mma16816(acc[mt][nb], ah[mt],
                         bh[nb >> 1][(nb & 1) * 2], bh[nb >> 1][(nb & 1) * 2 + 1]);
    }
}

// ---------------- single-tile GEMM (expm / tables) ----------------------------
__device__ __forceinline__ void gemm8(const f16* __restrict__ Ah, const f16* __restrict__ Al,
                                      const f16* __restrict__ Bh, const f16* __restrict__ Bl,
                                      int mo, int no, float acc[2][4][4])
{
    extern __shared__ char sm[];
    const uint32_t smb = smem_u32(sm);
    const int tid = threadIdx.x, lane = tid & 31, wid = tid >> 5;
    const int m0w = (wid & 3) * 32, n0w = (wid >> 2) * 32;
    const int lr = tid >> 2, cc = tid & 3;

    const f16* gAh = Ah + (size_t)(mo + lr) * DIM + cc * 8;
    const f16* gAl = Al + (size_t)(mo + lr) * DIM + cc * 8;
    const f16* gBh = Bh + (size_t)(no + lr) * DIM + cc * 8;
    const f16* gBl = Bl + (size_t)(no + lr) * DIM + cc * 8;
    const uint32_t sd0 = swz((uint32_t)lr, (uint32_t)cc * 16u);

    #pragma unroll
    for (int mt = 0; mt < 2; ++mt)
        #pragma unroll
        for (int nb = 0; nb < 4; ++nb)
            #pragma unroll
            for (int q = 0; q < 4; ++q) acc[mt][nb][q] = 0.0f;

    auto issue = [&](int c) {
        const uint32_t st = smb + (uint32_t)(c & (DEPTH - 1)) * STAGEB;
        const int ge = c * 32;
        cp16(st + sd0,             gAh + ge);
        cp16(st + sd0 + TILEB,     gAl + ge);
        cp16(st + sd0 + 2*TILEB,   gBh + ge);
        cp16(st + sd0 + 3*TILEB,   gBl + ge);
    };

    #pragma unroll
    for (int p = 0; p < DEPTH - 1; ++p) { issue(p); cp_commit(); }

    for (int c = 0; c < 8; ++c) {
        cp_wait2();
        __syncthreads();
        if (c + DEPTH - 1 < 8) issue(c + DEPTH - 1);
        cp_commit();
        mma_chunk3(smb + (uint32_t)(c & (DEPTH - 1)) * STAGEB, lane, m0w, n0w, acc);
    }
}

// ---------------- staged split epilogue (expm / tables) -----------------------
__device__ __forceinline__ void epi_split(float acc[2][4][4], float alpha, int addI,
                                          int mo, int no,
                                          f16* __restrict__ oAh, f16* __restrict__ oAl,
                                          f16* __restrict__ oBh, f16* __restrict__ oBl)
{
    extern __shared__ char sm[];
    float* sf = (float*)sm;
    const int tid = threadIdx.x, lane = tid & 31, wid = tid >> 5;
    const int m0w = (wid & 3) * 32, n0w = (wid >> 2) * 32;
    const int r0 = lane >> 2, cq = (lane & 3) * 2;

    __syncthreads();
    #pragma unroll
    for (int mt = 0; mt < 2; ++mt)
        #pragma unroll
        for (int half = 0; half < 2; ++half) {
            const int row = m0w + mt * 16 + r0 + half * 8;
            const int gr = mo + row;
            #pragma unroll
            for (int nb = 0; nb < 4; ++nb) {
                const int col = n0w + nb * 8 + cq;
                const int gc = no + col;
                float v0 = alpha * acc[mt][nb][half * 2 + 0];
                float v1 = alpha * acc[mt][nb][half * 2 + 1];
                if (addI) {
                    if (gr == gc)     v0 += 1.0f;
                    if (gr == gc + 1) v1 += 1.0f;
                }
                sf[row * PITCH + col]     = v0;
                sf[row * PITCH + col + 1] = v1;
            }
        }
    __syncthreads();

    if (oAh) {
        const int r = tid & 127, cg = tid >> 7;
        const int c0 = cg * 32;
        uint32_t hv[16], lv[16];
        #pragma unroll
        for (int j = 0; j < 16; ++j)
            hv[j] = pack_hi(sf[r * PITCH + c0 + 2*j], sf[r * PITCH + c0 + 2*j + 1], lv[j]);
        uint4* dh = (uint4*)(oAh + (size_t)(mo + r) * DIM + no + c0);
        uint4* dl = (uint4*)(oAl + (size_t)(mo + r) * DIM + no + c0);
        #pragma unroll
        for (int q = 0; q < 4; ++q) {
            dh[q] = make_uint4(hv[4*q], hv[4*q+1], hv[4*q+2], hv[4*q+3]);
            dl[q] = make_uint4(lv[4*q], lv[4*q+1], lv[4*q+2], lv[4*q+3]);
        }
    }
    {
        const int c = tid & 127, rg = tid >> 7;
        const int rb = rg * 32;
        uint32_t hv[16], lv[16];
        #pragma unroll
        for (int j = 0; j < 16; ++j)
            hv[j] = pack_hi(sf[(rb + 2*j) * PITCH + c], sf[(rb + 2*j + 1) * PITCH + c], lv[j]);
        uint4* dh = (uint4*)(oBh + (size_t)(no + c) * DIM + mo + rb);
        uint4* dl = (uint4*)(oBl + (size_t)(no + c) * DIM + mo + rb);
        #pragma unroll
        for (int q = 0; q < 4; ++q) {
            dh[q] = make_uint4(hv[4*q], hv[4*q+1], hv[4*q+2], hv[4*q+3]);
            dl[q] = make_uint4(lv[4*q], lv[4*q+1], lv[4*q+2], lv[4*q+3]);
        }
    }
    __syncthreads();
}

// ---------------- kernels -----------------------------------------------------
__global__ void k_skew(const float* __restrict__ prim, f16* TBh, f16* TBl)
{
    int idx = blockIdx.x * blockDim.x + threadIdx.x;
    if (idx >= 2 * MATSZ) return;
    int b = idx >> 16, ij = idx & 65535, i = ij >> 8, j = ij & 255;
    float a = (prim[(size_t)b * MATSZ + (size_t)j * DIM + i] -
               prim[(size_t)b * MATSZ + (size_t)i * DIM + j]) * 0.125f;
    f16 h = __float2half(a);
    g_eAh[idx] = h;
    g_eAl[idx] = __float2half(a - __half2float(h));
    float d = (i == j) ? 1.0f : 0.0f;
    float tb = d - a * (1.0f / 6.0f);
    f16 th = __float2half(tb);
    TBh[idx] = th;
    TBl[idx] = __float2half(tb - __half2float(th));
}

__global__ __launch_bounds__(512, 1)
void k_gemm_split(const f16* Ah, const f16* Al, const f16* Bh, const f16* Bl,
                  f16* oAh, f16* oAl, f16* oBh, f16* oBl, float alpha, int addI)
{
    const size_t off = (size_t)blockIdx.z * MATSZ;
    const int mo = blockIdx.y * 128, no = blockIdx.x * 128;
    float acc[2][4][4];
    gemm8(Ah + off, Al + off, Bh + off, Bl + off, mo, no, acc);
    epi_split(acc, alpha, addI, mo, no,
              oAh ? oAh + off : nullptr, oAl ? oAl + off : nullptr,
              oBh + off, oBl + off);
}

__global__ __launch_bounds__(512, 1)
void k_tab(int lvl)
{
    const int c = blockIdx.z;
    const int lb = lvl - 1;
    const size_t aoff = (size_t)(((1 << lb) - 2) + (c & ((1 << lb) - 1))) * MATSZ;
    const size_t boff = (size_t)(c >> lb) * MATSZ;
    const size_t ooff = (size_t)(((1 << lvl) - 2) + c) * MATSZ;
    const int mo = blockIdx.y * 128, no = blockIdx.x * 128;
    float acc[2][4][4];
    gemm8(g_tabAh + aoff, g_tabAl + aoff, g_tabBh + boff, g_tabBl + boff, mo, no, acc);
    epi_split(acc, 1.0f, 0, mo, no,
              g_tabAh + ooff, g_tabAl + ooff, g_tabBh + ooff, g_tabBl + ooff);
}

// ---------------- persistent leaf kernel (1-product fp16) ---------------------
__global__ __launch_bounds__(512, 1)
void k_leaf(const int* __restrict__ unique, float* __restrict__ out)
{
    extern __shared__ char sm[];
    const uint32_t smb = smem_u32(sm);
    uint4* metaM = (uint4*)(sm + STAGESB);
    uint4* metaC = metaM + 60;
    __shared__ int cntM, cntC;
    const int tid = threadIdx.x, lane = tid & 31, wid = tid >> 5;
    const int m0w = (wid & 3) * 32, n0w = (wid >> 2) * 32;
    const int bid = blockIdx.x;

    if (tid == 0) { cntM = 0; cntC = 0; }
    __syncthreads();

    {
        const int w = bid + tid * PGRID;
        if (w < NITEMS) {
            const int n = w >> 2, tile = w & 3;
            const unsigned p = (unsigned)unique[n];
            const int len = 31 - __clz((int)p);
            if (len >= 9) {
                const uint32_t aIdx = 254u + (p & 255u);
                const int hb = len - 8;
                const uint32_t bIdx = ((1u << hb) - 2u) + ((p >> 8) & ((1u << hb) - 1u));
                const int s = atomicAdd(&cntM, 1);
                metaM[s] = make_uint4(aIdx, bIdx, (uint32_t)((n << 2) | tile), 0);
            } else {
                const uint32_t sIdx = (len >= 1)
                    ? (((1u << len) - 2u) + (p & ((1u << len) - 1u))) : 0xFFFFFFFFu;
                const int s = atomicAdd(&cntC, 1);
                metaC[s] = make_uint4(sIdx, 0, (uint32_t)((n << 2) | tile), 0);
            }
        }
    }
    __syncthreads();

    // copy / identity items (full precision via hi+lo)
    for (int i = 0; i < cntC; ++i) {
        const uint4 mt4 = metaC[i];
        const int n = (int)(mt4.z >> 2), tile = (int)(mt4.z & 3);
        const int mo = (tile >> 1) * 128, no = (tile & 1) * 128;
        float* C = out + (size_t)n * MATSZ;
        const int r = tid >> 2, cb = (tid & 3) * 32;
        if (mt4.x != 0xFFFFFFFFu) {
            const f16* sh = g_tabAh + (size_t)mt4.x * MATSZ + (size_t)(mo + r) * DIM + no + cb;
            const f16* sl = g_tabAl + (size_t)mt4.x * MATSZ + (size_t)(mo + r) * DIM + no + cb;
            float* d = C + (size_t)(mo + r) * DIM + no + cb;
            #pragma unroll
            for (int j = 0; j < 16; ++j) {
                __half2 h = *(const __half2*)(sh + 2*j);
                __half2 l = *(const __half2*)(sl + 2*j);
                *(float2*)(d + 2*j) =
                    make_float2(__half2float(h.x) + __half2float(l.x),
                                __half2float(h.y) + __half2float(l.y));
            }
        } else {
            float* d = C + (size_t)(mo + r) * DIM + no + cb;
            #pragma unroll
            for (int j = 0; j < 32; ++j)
                d[j] = ((mo + r) == (no + cb + j)) ? 1.0f : 0.0f;
        }
    }

    const int G = cntM * 8;
    if (G == 0) return;
    const int lr = tid >> 2, cc = tid & 3;
    const uint32_t sd0 = swz((uint32_t)lr, (uint32_t)cc * 16u);
    const size_t rowOffA = (size_t)lr * DIM + cc * 8;

    auto issue = [&](int g) {
        const uint4 mt4 = metaM[g >> 3];
        const int c = g & 7, tile = (int)(mt4.z & 3);
        const int mo = (tile >> 1) * 128, no = (tile & 1) * 128;
        const uint32_t st = smb + (uint32_t)(g & (DEPTH - 1)) * LSTAGEB;
        const size_t ao = (size_t)mt4.x * MATSZ + (size_t)mo * DIM + rowOffA + c * 32;
        const size_t bo = (size_t)mt4.y * MATSZ + (size_t)no * DIM + rowOffA + c * 32;
        cp16(st + sd0,         g_tabAh + ao);
        cp16(st + sd0 + TILEB, g_tabBh + bo);
    };

    float acc[2][4][4];
    #pragma unroll
    for (int mt = 0; mt < 2; ++mt)
        #pragma unroll
        for (int nb = 0; nb < 4; ++nb)
            #pragma unroll
            for (int q = 0; q < 4; ++q) acc[mt][nb][q] = 0.0f;

    #pragma unroll
    for (int p = 0; p < DEPTH - 1; ++p) {
        if (p < G) issue(p);
        cp_commit();
    }

    for (int g = 0; g < G; ++g) {
        cp_wait2();
        __syncthreads();
        if (g + DEPTH - 1 < G) issue(g + DEPTH - 1);
        cp_commit();
        mma_chunk1(smb + (uint32_t)(g & (DEPTH - 1)) * LSTAGEB, lane, m0w, n0w, acc);

        if ((g & 7) == 7) {
            const uint4 mt4 = metaM[g >> 3];
            const int n = (int)(mt4.z >> 2), tile = (int)(mt4.z & 3);
            const int mo = (tile >> 1) * 128, no = (tile & 1) * 128;
            float* C = out + (size_t)n * MATSZ;
            const int r0 = lane >> 2, cq = (lane & 3) * 2;
            #pragma unroll
            for (int mt = 0; mt < 2; ++mt)
                #pragma unroll
                for (int half = 0; half < 2; ++half) {
                    const int gr = mo + m0w + mt * 16 + r0 + half * 8;
                    #pragma unroll
                    for (int nb = 0; nb < 4; ++nb) {
                        const int gc = no + n0w + nb * 8 + cq;
                        *(float2*)(C + (size_t)gr * DIM + gc) =
                            make_float2(acc[mt][nb][half * 2], acc[mt][nb][half * 2 + 1]);
                        acc[mt][nb][half * 2] = 0.0f;
                        acc[mt][nb][half * 2 + 1] = 0.0f;
                    }
                }
        }
    }
}

// ---------------- host orchestration -----------------------------------------
extern "C" void kernel_launch(void* const* d_in, const int* in_sizes, int n_in,
                              void* d_out, int out_size)
{
    const float* prim   = (const float*)d_in[0];
    const int*   unique = (const int*)d_in[2];
    float*       out    = (float*)d_out;
    (void)in_sizes; (void)n_in; (void)out_size;

    cudaFuncSetAttribute(k_gemm_split, cudaFuncAttributeMaxDynamicSharedMemorySize, SMEM_DYN);
    cudaFuncSetAttribute(k_tab,  cudaFuncAttributeMaxDynamicSharedMemorySize, SMEM_DYN);
    cudaFuncSetAttribute(k_leaf, cudaFuncAttributeMaxDynamicSharedMemorySize, SMEM_DYN);

    f16 *eAh, *eAl, *TAh, *TAl, *TBh, *TBl, *tAh, *tAl, *tBh, *tBl;
    cudaGetSymbolAddress((void**)&eAh, g_eAh);
    cudaGetSymbolAddress((void**)&eAl, g_eAl);
    cudaGetSymbolAddress((void**)&TAh, g_TAh);
    cudaGetSymbolAddress((void**)&TAl, g_TAl);
    cudaGetSymbolAddress((void**)&TBh, g_TBh);
    cudaGetSymbolAddress((void**)&TBl, g_TBl);
    cudaGetSymbolAddress((void**)&tAh, g_tabAh);
    cudaGetSymbolAddress((void**)&tAl, g_tabAl);
    cudaGetSymbolAddress((void**)&tBh, g_tabBh);
    cudaGetSymbolAddress((void**)&tBl, g_tabBl);

    auto TA_h = [&](int i) { return TAh + (size_t)i * 2 * MATSZ; };
    auto TA_l = [&](int i) { return TAl + (size_t)i * 2 * MATSZ; };
    auto TB_h = [&](int i) { return TBh + (size_t)i * 2 * MATSZ; };
    auto TB_l = [&](int i) { return TBl + (size_t)i * 2 * MATSZ; };

    const dim3 g222(2, 2, 2), blk(512);

    k_skew<<<(2 * MATSZ + 255) / 256, 256>>>(prim, TB_h(0), TB_l(0));

    int cur = 0;
    for (int k = 5; k >= 1; --k) {
        const int nxt = cur ^ 1;
        const bool last = (k == 1);
        k_gemm_split<<<g222, blk, SMEM_DYN>>>(
            eAh, eAl, TB_h(cur), TB_l(cur),
            last ? TA_h(nxt) : nullptr, last ? TA_l(nxt) : nullptr,
            TB_h(nxt), TB_l(nxt), 1.0f / (float)k, 1);
        cur = nxt;
    }
    for (int sq = 0; sq < 3; ++sq) {
        const int nxt = cur ^ 1;
        const bool last = (sq == 2);
        k_gemm_split<<<g222, blk, SMEM_DYN>>>(
            TA_h(cur), TA_l(cur), TB_h(cur), TB_l(cur),
            last ? tAh : TA_h(nxt), last ? tAl : TA_l(nxt),
            last ? tBh : TB_h(nxt), last ? tBl : TB_l(nxt), 1.0f, 0);
        cur = nxt;
    }

    for (int lvl = 2; lvl <= 8; ++lvl)
        k_tab<<<dim3(2, 2, 1 << lvl), blk, SMEM_DYN>>>(lvl);

    k_leaf<<<PGRID, blk, SMEM_DYN>>>(unique, out);
}

// round 7
// speedup vs baseline: 4.7674x; 1.2759x over previous
#include <cuda_runtime.h>
#include <cuda_fp16.h>
#include <cstdint>

#define DIM 256
#define MATSZ (DIM*DIM)
#define NPOS 2048
#define NITEMS (NPOS*4)
#define PGRID 148
#define DEPTH 4
#define BT 8192                 // B tile: 128 rows * 64B
#define PITCH 129

#define SM_EXPM  (DEPTH*24576)          // MW=2,NPROD=3: 2*4096+2*8192 per stage
#define SM_TAB2  (DEPTH*20480)          // MW=2,NPROD=2: 4096+2*8192
#define SM_TAB4  (DEPTH*24576)          // MW=4,NPROD=2: 8192+2*8192
#define SM_LEAF  (DEPTH*16384 + 2048)   // MW=4,NPROD=1: 8192+8192, + meta

using f16 = __half;

// ---------------- static device scratch --------------------------------------
__device__ f16 g_eAh[2*MATSZ], g_eAl[2*MATSZ];
__device__ f16 g_TAh[2][2*MATSZ], g_TAl[2][2*MATSZ];
__device__ f16 g_TBh[2][2*MATSZ], g_TBl[2][2*MATSZ];
__device__ f16 g_tabAh[510*MATSZ];                    // A-layout hi (all levels)
__device__ f16 g_tabBh[510*MATSZ], g_tabBl[510*MATSZ]; // B-layout; lo used only lvl-1

// ---------------- helpers -----------------------------------------------------
__device__ __forceinline__ uint32_t smem_u32(const void* p) {
    uint32_t a;
    asm("{ .reg .u64 t; cvta.to.shared.u64 t, %1; cvt.u32.u64 %0, t; }" : "=r"(a) : "l"(p));
    return a;
}
__device__ __forceinline__ void ldm4(uint32_t a[4], uint32_t addr) {
    asm volatile("ldmatrix.sync.aligned.m8n8.x4.shared.b16 {%0,%1,%2,%3}, [%4];"
                 : "=r"(a[0]), "=r"(a[1]), "=r"(a[2]), "=r"(a[3]) : "r"(addr));
}
__device__ __forceinline__ void mma16816(float c[4], const uint32_t a[4],
                                         uint32_t b0, uint32_t b1) {
    asm volatile("mma.sync.aligned.m16n8k16.row.col.f32.f16.f16.f32 "
                 "{%0,%1,%2,%3}, {%4,%5,%6,%7}, {%8,%9}, {%0,%1,%2,%3};"
                 : "+f"(c[0]), "+f"(c[1]), "+f"(c[2]), "+f"(c[3])
                 : "r"(a[0]), "r"(a[1]), "r"(a[2]), "r"(a[3]), "r"(b0), "r"(b1));
}
__device__ __forceinline__ void cp16(uint32_t s, const void* g) {
    asm volatile("cp.async.cg.shared.global [%0], [%1], 16;" :: "r"(s), "l"(g));
}
__device__ __forceinline__ void cp_commit() {
    asm volatile("cp.async.commit_group;" ::: "memory");
}
__device__ __forceinline__ void cp_wait2() {
    asm volatile("cp.async.wait_group 2;" ::: "memory");
}
__device__ __forceinline__ uint32_t swz(uint32_t row, uint32_t byteInRow) {
    uint32_t chunk = byteInRow >> 4;
    return row * 64u + ((chunk ^ ((row >> 1) & 3u)) << 4) + (byteInRow & 15u);
}
__device__ __forceinline__ uint32_t pack_hi(float f0, float f1, uint32_t& lo) {
    f16 h0 = __float2half(f0), h1 = __float2half(f1);
    f16 l0 = __float2half(f0 - __half2float(h0));
    f16 l1 = __float2half(f1 - __half2float(h1));
    __half2 hh = __halves2half2(h0, h1);
    __half2 ll = __halves2half2(l0, l1);
    lo = *(uint32_t*)&ll;
    return *(uint32_t*)&hh;
}

// ---------------- templated chunk MMA ----------------------------------------
// NPROD: 3 = ah*bh + ah*bl + al*bh ; 2 = ah*bh + ah*bl ; 1 = ah*bh
template<int NPROD>
__device__ __forceinline__ void mma_chunk(uint32_t aBase, uint32_t aLo,
                                          uint32_t bBase, uint32_t bLo,
                                          int lane, int m0w, int n0w, float acc[2][4][4])
{
    #pragma unroll
    for (int s = 0; s < 2; ++s) {
        uint32_t ah[2][4], al[2][4], bh[2][4], bl[2][4];
        #pragma unroll
        for (int mt = 0; mt < 2; ++mt) {
            const uint32_t off = swz((uint32_t)(m0w + mt * 16 + (lane & 15)),
                                     (uint32_t)(s * 32 + ((lane & 16) ? 16 : 0)));
            ldm4(ah[mt], aBase + off);
            if (NPROD == 3) ldm4(al[mt], aLo + off);
        }
        #pragma unroll
        for (int nt = 0; nt < 2; ++nt) {
            const uint32_t off = swz((uint32_t)(n0w + nt * 16 + (lane & 7) + ((lane & 16) ? 8 : 0)),
                                     (uint32_t)(s * 32 + ((lane & 8) ? 16 : 0)));
            ldm4(bh[nt], bBase + off);
            if (NPROD >= 2) ldm4(bl[nt], bLo + off);
        }
        #pragma unroll
        for (int mt = 0; mt < 2; ++mt)
            #pragma unroll
            for (int nb = 0; nb < 4; ++nb) {
                const uint32_t b0h = bh[nb >> 1][(nb & 1) * 2];
                const uint32_t b1h = bh[nb >> 1][(nb & 1) * 2 + 1];
                mma16816(acc[mt][nb], ah[mt], b0h, b1h);
                if (NPROD >= 2)
                    mma16816(acc[mt][nb], ah[mt],
                             bl[nb >> 1][(nb & 1) * 2], bl[nb >> 1][(nb & 1) * 2 + 1]);
                if (NPROD == 3)
                    mma16816(acc[mt][nb], al[mt], b0h, b1h);
            }
    }
}

// ---------------- templated pipelined GEMM ------------------------------------
// Pointers pre-offset so row r element = P + r*DIM (+ k offset added inside).
template<int MW, int NPROD>
__device__ __forceinline__ void gemm_run(
    const f16* __restrict__ Ah, const f16* __restrict__ Al,
    const f16* __restrict__ Bh, const f16* __restrict__ Bl,
    float acc[2][4][4])
{
    constexpr int MTILE  = 32 * MW;
    constexpr int NTHR   = 128 * MW;
    constexpr int ATILEB = MTILE * 64;
    constexpr int NA = (NPROD == 3) ? 2 : 1;
    constexpr int NB = (NPROD >= 2) ? 2 : 1;
    constexpr uint32_t STG = (uint32_t)(NA * ATILEB + NB * BT);

    extern __shared__ char sm[];
    const uint32_t smb = smem_u32(sm);
    const int tid = threadIdx.x, lane = tid & 31, wid = tid >> 5;
    const int m0w = (wid % MW) * 32, n0w = (wid / MW) * 32;
    const int lr = tid >> 2, cc = tid & 3;
    const uint32_t sdr = swz((uint32_t)lr, (uint32_t)cc * 16u);

    #pragma unroll
    for (int mt = 0; mt < 2; ++mt)
        #pragma unroll
        for (int nb = 0; nb < 4; ++nb)
            #pragma unroll
            for (int q = 0; q < 4; ++q) acc[mt][nb][q] = 0.0f;

    auto issue = [&](int c) {
        const uint32_t st = smb + (uint32_t)(c & (DEPTH - 1)) * STG;
        // A tile: MTILE rows, one pass (NTHR/4 == MTILE)
        {
            const size_t go = (size_t)lr * DIM + c * 32 + cc * 8;
            cp16(st + sdr, Ah + go);
            if (NPROD == 3) cp16(st + sdr + ATILEB, Al + go);
        }
        // B tile: 128 rows
        #pragma unroll
        for (int rr = 0; rr < 128; rr += NTHR / 4) {
            const int r = lr + rr;
            const uint32_t sd = st + (uint32_t)(NA * ATILEB) + swz((uint32_t)r, (uint32_t)cc * 16u);
            const size_t go = (size_t)r * DIM + c * 32 + cc * 8;
            cp16(sd, Bh + go);
            if (NPROD >= 2) cp16(sd + BT, Bl + go);
        }
    };

    #pragma unroll
    for (int p = 0; p < DEPTH - 1; ++p) { issue(p); cp_commit(); }

    for (int c = 0; c < 8; ++c) {
        cp_wait2();
        __syncthreads();
        if (c + DEPTH - 1 < 8) issue(c + DEPTH - 1);
        cp_commit();
        const uint32_t st = smb + (uint32_t)(c & (DEPTH - 1)) * STG;
        mma_chunk<NPROD>(st, st + ATILEB, st + NA * ATILEB, st + NA * ATILEB + BT,
                         lane, m0w, n0w, acc);
    }
}

// ---------------- templated staged epilogue -----------------------------------
template<int MW>
__device__ __forceinline__ void epi_split(float acc[2][4][4], float alpha, int addI,
                                          int mo, int no,
                                          f16* __restrict__ oAh, f16* __restrict__ oAl,
                                          f16* __restrict__ oBh, f16* __restrict__ oBl)
{
    extern __shared__ char sm[];
    float* sf = (float*)sm;
    const int tid = threadIdx.x, lane = tid & 31, wid = tid >> 5;
    const int m0w = (wid % MW) * 32, n0w = (wid / MW) * 32;
    const int r0 = lane >> 2, cq = (lane & 3) * 2;

    __syncthreads();
    #pragma unroll
    for (int mt = 0; mt < 2; ++mt)
        #pragma unroll
        for (int half = 0; half < 2; ++half) {
            const int row = m0w + mt * 16 + r0 + half * 8;
            const int gr = mo + row;
            #pragma unroll
            for (int nb = 0; nb < 4; ++nb) {
                const int col = n0w + nb * 8 + cq;
                const int gc = no + col;
                float v0 = alpha * acc[mt][nb][half * 2 + 0];
                float v1 = alpha * acc[mt][nb][half * 2 + 1];
                if (addI) {
                    if (gr == gc)     v0 += 1.0f;
                    if (gr == gc + 1) v1 += 1.0f;
                }
                sf[row * PITCH + col]     = v0;
                sf[row * PITCH + col + 1] = v1;
            }
        }
    __syncthreads();

    if (oAh) {
        const int r = tid >> 2, c0 = (tid & 3) * 32;
        uint32_t hv[16], lv[16];
        #pragma unroll
        for (int j = 0; j < 16; ++j)
            hv[j] = pack_hi(sf[r * PITCH + c0 + 2*j], sf[r * PITCH + c0 + 2*j + 1], lv[j]);
        uint4* dh = (uint4*)(oAh + (size_t)(mo + r) * DIM + no + c0);
        #pragma unroll
        for (int q = 0; q < 4; ++q)
            dh[q] = make_uint4(hv[4*q], hv[4*q+1], hv[4*q+2], hv[4*q+3]);
        if (oAl) {
            uint4* dl = (uint4*)(oAl + (size_t)(mo + r) * DIM + no + c0);
            #pragma unroll
            for (int q = 0; q < 4; ++q)
                dl[q] = make_uint4(lv[4*q], lv[4*q+1], lv[4*q+2], lv[4*q+3]);
        }
    }
    {
        const int c = tid & 127, rg = tid >> 7;
        const int rb = rg * 32;
        uint32_t hv[16], lv[16];
        #pragma unroll
        for (int j = 0; j < 16; ++j)
            hv[j] = pack_hi(sf[(rb + 2*j) * PITCH + c], sf[(rb + 2*j + 1) * PITCH + c], lv[j]);
        uint4* dh = (uint4*)(oBh + (size_t)(no + c) * DIM + mo + rb);
        #pragma unroll
        for (int q = 0; q < 4; ++q)
            dh[q] = make_uint4(hv[4*q], hv[4*q+1], hv[4*q+2], hv[4*q+3]);
        if (oBl) {
            uint4* dl = (uint4*)(oBl + (size_t)(no + c) * DIM + mo + rb);
            #pragma unroll
            for (int q = 0; q < 4; ++q)
                dl[q] = make_uint4(lv[4*q], lv[4*q+1], lv[4*q+2], lv[4*q+3]);
        }
    }
    __syncthreads();
}

// ---------------- kernels -----------------------------------------------------
__global__ void k_skew(const float* __restrict__ prim, f16* TBh, f16* TBl)
{
    int idx = blockIdx.x * blockDim.x + threadIdx.x;
    if (idx >= 2 * MATSZ) return;
    int b = idx >> 16, ij = idx & 65535, i = ij >> 8, j = ij & 255;
    float a = (prim[(size_t)b * MATSZ + (size_t)j * DIM + i] -
               prim[(size_t)b * MATSZ + (size_t)i * DIM + j]) * 0.125f;
    f16 h = __float2half(a);
    g_eAh[idx] = h;
    g_eAl[idx] = __float2half(a - __half2float(h));
    float d = (i == j) ? 1.0f : 0.0f;
    float tb = d - a * (1.0f / 6.0f);
    f16 th = __float2half(tb);
    TBh[idx] = th;
    TBl[idx] = __float2half(tb - __half2float(th));
}

// expm round: MW=2, NPROD=3. grid (2, 4, 2), block 256.
__global__ __launch_bounds__(256, 1)
void k_gemm_split(const f16* Ah, const f16* Al, const f16* Bh, const f16* Bl,
                  f16* oAh, f16* oAl, f16* oBh, f16* oBl, float alpha, int addI)
{
    const size_t off = (size_t)blockIdx.z * MATSZ;
    const int mo = blockIdx.y * 64, no = blockIdx.x * 128;
    float acc[2][4][4];
    gemm_run<2, 3>(Ah + off + (size_t)mo * DIM, Al + off + (size_t)mo * DIM,
                   Bh + off + (size_t)no * DIM, Bl + off + (size_t)no * DIM, acc);
    epi_split<2>(acc, alpha, addI, mo, no,
                 oAh ? oAh + off : nullptr, oAl ? oAl + off : nullptr,
                 oBh + off, oBl ? oBl + off : nullptr);
}

// table level build: NPROD=2 (A hi only, B = M split). Template MW.
template<int MW>
__global__ __launch_bounds__(128 * MW, 1)
void k_tab(int lvl)
{
    const int c = blockIdx.z;
    const int lb = lvl - 1;
    const size_t aoff = (size_t)(((1 << lb) - 2) + (c & ((1 << lb) - 1))) * MATSZ;
    const size_t boff = (size_t)(c >> lb) * MATSZ;
    const size_t ooff = (size_t)(((1 << lvl) - 2) + c) * MATSZ;
    const int mo = blockIdx.y * (32 * MW), no = blockIdx.x * 128;
    float acc[2][4][4];
    gemm_run<MW, 2>(g_tabAh + aoff + (size_t)mo * DIM, nullptr,
                    g_tabBh + boff + (size_t)no * DIM,
                    g_tabBl + boff + (size_t)no * DIM, acc);
    epi_split<MW>(acc, 1.0f, 0, mo, no,
                  g_tabAh + ooff, nullptr, g_tabBh + ooff, nullptr);
}

// ---------------- persistent leaf kernel (1-product) --------------------------
__global__ __launch_bounds__(512, 1)
void k_leaf(const int* __restrict__ unique, float* __restrict__ out)
{
    extern __shared__ char sm[];
    const uint32_t smb = smem_u32(sm);
    uint4* metaM = (uint4*)(sm + DEPTH * 16384);
    uint4* metaC = metaM + 60;
    __shared__ int cntM, cntC;
    const int tid = threadIdx.x, lane = tid & 31, wid = tid >> 5;
    const int m0w = (wid & 3) * 32, n0w = (wid >> 2) * 32;
    const int bid = blockIdx.x;

    if (tid == 0) { cntM = 0; cntC = 0; }
    __syncthreads();

    {
        const int w = bid + tid * PGRID;
        if (w < NITEMS) {
            const int n = w >> 2, tile = w & 3;
            const unsigned p = (unsigned)unique[n];
            const int len = 31 - __clz((int)p);
            if (len >= 9) {
                const uint32_t aIdx = 254u + (p & 255u);
                const int hb = len - 8;
                const uint32_t bIdx = ((1u << hb) - 2u) + ((p >> 8) & ((1u << hb) - 1u));
                const int s = atomicAdd(&cntM, 1);
                metaM[s] = make_uint4(aIdx, bIdx, (uint32_t)((n << 2) | tile), 0);
            } else {
                const uint32_t sIdx = (len >= 1)
                    ? (((1u << len) - 2u) + (p & ((1u << len) - 1u))) : 0xFFFFFFFFu;
                const int s = atomicAdd(&cntC, 1);
                metaC[s] = make_uint4(sIdx, 0, (uint32_t)((n << 2) | tile), 0);
            }
        }
    }
    __syncthreads();

    // copy / identity items (hi-part copy; rounding ~1e-4, within budget)
    for (int i = 0; i < cntC; ++i) {
        const uint4 mt4 = metaC[i];
        const int n = (int)(mt4.z >> 2), tile = (int)(mt4.z & 3);
        const int mo = (tile >> 1) * 128, no = (tile & 1) * 128;
        float* C = out + (size_t)n * MATSZ;
        const int r = tid >> 2, cb = (tid & 3) * 32;
        float* d = C + (size_t)(mo + r) * DIM + no + cb;
        if (mt4.x != 0xFFFFFFFFu) {
            const f16* sh = g_tabAh + (size_t)mt4.x * MATSZ + (size_t)(mo + r) * DIM + no + cb;
            #pragma unroll
            for (int j = 0; j < 16; ++j) {
                __half2 h = *(const __half2*)(sh + 2*j);
                *(float2*)(d + 2*j) = make_float2(__half2float(h.x), __half2float(h.y));
            }
        } else {
            #pragma unroll
            for (int j = 0; j < 32; ++j)
                d[j] = ((mo + r) == (no + cb + j)) ? 1.0f : 0.0f;
        }
    }

    const int G = cntM * 8;
    if (G == 0) return;
    const int lr = tid >> 2, cc = tid & 3;
    const uint32_t sd0 = swz((uint32_t)lr, (uint32_t)cc * 16u);
    const size_t rowOffA = (size_t)lr * DIM + cc * 8;

    auto issue = [&](int g) {
        const uint4 mt4 = metaM[g >> 3];
        const int c = g & 7, tile = (int)(mt4.z & 3);
        const int mo = (tile >> 1) * 128, no = (tile & 1) * 128;
        const uint32_t st = smb + (uint32_t)(g & (DEPTH - 1)) * 16384u;
        const size_t ao = (size_t)mt4.x * MATSZ + (size_t)mo * DIM + rowOffA + c * 32;
        const size_t bo = (size_t)mt4.y * MATSZ + (size_t)no * DIM + rowOffA + c * 32;
        cp16(st + sd0,        g_tabAh + ao);
        cp16(st + sd0 + 8192, g_tabBh + bo);
    };

    float acc[2][4][4];
    #pragma unroll
    for (int mt = 0; mt < 2; ++mt)
        #pragma unroll
        for (int nb = 0; nb < 4; ++nb)
            #pragma unroll
            for (int q = 0; q < 4; ++q) acc[mt][nb][q] = 0.0f;

    #pragma unroll
    for (int p = 0; p < DEPTH - 1; ++p) {
        if (p < G) issue(p);
        cp_commit();
    }

    for (int g = 0; g < G; ++g) {
        cp_wait2();
        __syncthreads();
        if (g + DEPTH - 1 < G) issue(g + DEPTH - 1);
        cp_commit();
        const uint32_t st = smb + (uint32_t)(g & (DEPTH - 1)) * 16384u;
        mma_chunk<1>(st, 0, st + 8192, 0, lane, m0w, n0w, acc);

        if ((g & 7) == 7) {
            const uint4 mt4 = metaM[g >> 3];
            const int n = (int)(mt4.z >> 2), tile = (int)(mt4.z & 3);
            const int mo = (tile >> 1) * 128, no = (tile & 1) * 128;
            float* C = out + (size_t)n * MATSZ;
            const int r0 = lane >> 2, cq = (lane & 3) * 2;
            #pragma unroll
            for (int mt = 0; mt < 2; ++mt)
                #pragma unroll
                for (int half = 0; half < 2; ++half) {
                    const int gr = mo + m0w + mt * 16 + r0 + half * 8;
                    #pragma unroll
                    for (int nb = 0; nb < 4; ++nb) {
                        const int gc = no + n0w + nb * 8 + cq;
                        *(float2*)(C + (size_t)gr * DIM + gc) =
                            make_float2(acc[mt][nb][half * 2], acc[mt][nb][half * 2 + 1]);
                        acc[mt][nb][half * 2] = 0.0f;
                        acc[mt][nb][half * 2 + 1] = 0.0f;
                    }
                }
        }
    }
}

// ---------------- host orchestration -----------------------------------------
extern "C" void kernel_launch(void* const* d_in, const int* in_sizes, int n_in,
                              void* d_out, int out_size)
{
    const float* prim   = (const float*)d_in[0];
    const int*   unique = (const int*)d_in[2];
    float*       out    = (float*)d_out;
    (void)in_sizes; (void)n_in; (void)out_size;

    cudaFuncSetAttribute(k_gemm_split, cudaFuncAttributeMaxDynamicSharedMemorySize, SM_EXPM);
    cudaFuncSetAttribute(k_tab<2>, cudaFuncAttributeMaxDynamicSharedMemorySize, SM_TAB2);
    cudaFuncSetAttribute(k_tab<4>, cudaFuncAttributeMaxDynamicSharedMemorySize, SM_TAB4);
    cudaFuncSetAttribute(k_leaf,   cudaFuncAttributeMaxDynamicSharedMemorySize, SM_LEAF);

    f16 *eAh, *eAl, *TAh, *TAl, *TBh, *TBl, *tAh, *tBh, *tBl;
    cudaGetSymbolAddress((void**)&eAh, g_eAh);
    cudaGetSymbolAddress((void**)&eAl, g_eAl);
    cudaGetSymbolAddress((void**)&TAh, g_TAh);
    cudaGetSymbolAddress((void**)&TAl, g_TAl);
    cudaGetSymbolAddress((void**)&TBh, g_TBh);
    cudaGetSymbolAddress((void**)&TBl, g_TBl);
    cudaGetSymbolAddress((void**)&tAh, g_tabAh);
    cudaGetSymbolAddress((void**)&tBh, g_tabBh);
    cudaGetSymbolAddress((void**)&tBl, g_tabBl);

    auto TA_h = [&](int i) { return TAh + (size_t)i * 2 * MATSZ; };
    auto TA_l = [&](int i) { return TAl + (size_t)i * 2 * MATSZ; };
    auto TB_h = [&](int i) { return TBh + (size_t)i * 2 * MATSZ; };
    auto TB_l = [&](int i) { return TBl + (size_t)i * 2 * MATSZ; };

    const dim3 gE(2, 4, 2);

    k_skew<<<(2 * MATSZ + 255) / 256, 256>>>(prim, TB_h(0), TB_l(0));

    int cur = 0;
    for (int k = 5; k >= 1; --k) {
        const int nxt = cur ^ 1;
        const bool last = (k == 1);
        k_gemm_split<<<gE, 256, SM_EXPM>>>(
            eAh, eAl, TB_h(cur), TB_l(cur),
            last ? TA_h(nxt) : nullptr, last ? TA_l(nxt) : nullptr,
            TB_h(nxt), TB_l(nxt), 1.0f / (float)k, 1);
        cur = nxt;
    }
    for (int sq = 0; sq < 3; ++sq) {
        const int nxt = cur ^ 1;
        const bool last = (sq == 2);
        k_gemm_split<<<gE, 256, SM_EXPM>>>(
            TA_h(cur), TA_l(cur), TB_h(cur), TB_l(cur),
            last ? tAh : TA_h(nxt), last ? nullptr : TA_l(nxt),
            last ? tBh : TB_h(nxt), last ? tBl : TB_l(nxt), 1.0f, 0);
        cur = nxt;
    }

    for (int lvl = 2; lvl <= 4; ++lvl)
        k_tab<2><<<dim3(2, 4, 1 << lvl), 256, SM_TAB2>>>(lvl);
    for (int lvl = 5; lvl <= 8; ++lvl)
        k_tab<4><<<dim3(2, 2, 1 << lvl), 512, SM_TAB4>>>(lvl);

    k_leaf<<<PGRID, 512, SM_LEAF>>>(unique, out);
}

// round 8
// speedup vs baseline: 5.1217x; 1.0743x over previous
#include <cuda_runtime.h>
#include <cuda_fp16.h>
#include <cstdint>

#define DIM 256
#define MATSZ (DIM*DIM)
#define NPOS 2048
#define NITEMS (NPOS*4)
#define PGRID 148
#define DEPTH 4
#define LDEPTH 8
#define BT 8192                 // B tile: 128 rows * 64B
#define PITCH 129

#define SM_EXPM  (DEPTH*20480)           // MW=1,NPROD=3: 2*2048 + 2*8192
#define SM_TAB2  (DEPTH*20480)           // MW=2,NPROD=2: 4096 + 2*8192
#define SM_LEAF  (LDEPTH*16384 + 2048)   // MW=4,NPROD=1: 8192+8192, + meta

using f16 = __half;

// ---------------- static device scratch --------------------------------------
__device__ f16 g_eAh[2*MATSZ], g_eAl[2*MATSZ];
__device__ f16 g_TAh[2][2*MATSZ], g_TAl[2][2*MATSZ];
__device__ f16 g_TBh[2][2*MATSZ], g_TBl[2][2*MATSZ];
__device__ f16 g_tabAh[510*MATSZ];                     // A-layout hi (all levels)
__device__ f16 g_tabBh[510*MATSZ], g_tabBl[510*MATSZ]; // B-layout; lo used only lvl-1

// ---------------- helpers -----------------------------------------------------
__device__ __forceinline__ uint32_t smem_u32(const void* p) {
    uint32_t a;
    asm("{ .reg .u64 t; cvta.to.shared.u64 t, %1; cvt.u32.u64 %0, t; }" : "=r"(a) : "l"(p));
    return a;
}
__device__ __forceinline__ void ldm4(uint32_t a[4], uint32_t addr) {
    asm volatile("ldmatrix.sync.aligned.m8n8.x4.shared.b16 {%0,%1,%2,%3}, [%4];"
                 : "=r"(a[0]), "=r"(a[1]), "=r"(a[2]), "=r"(a[3]) : "r"(addr));
}
__device__ __forceinline__ void mma16816(float c[4], const uint32_t a[4],
                                         uint32_t b0, uint32_t b1) {
    asm volatile("mma.sync.aligned.m16n8k16.row.col.f32.f16.f16.f32 "
                 "{%0,%1,%2,%3}, {%4,%5,%6,%7}, {%8,%9}, {%0,%1,%2,%3};"
                 : "+f"(c[0]), "+f"(c[1]), "+f"(c[2]), "+f"(c[3])
                 : "r"(a[0]), "r"(a[1]), "r"(a[2]), "r"(a[3]), "r"(b0), "r"(b1));
}
__device__ __forceinline__ void cp16(uint32_t s, const void* g) {
    asm volatile("cp.async.cg.shared.global [%0], [%1], 16;" :: "r"(s), "l"(g));
}
__device__ __forceinline__ void cp_commit() {
    asm volatile("cp.async.commit_group;" ::: "memory");
}
template<int N>
__device__ __forceinline__ void cp_wait() {
    asm volatile("cp.async.wait_group %0;" :: "n"(N) : "memory");
}
__device__ __forceinline__ uint32_t swz(uint32_t row, uint32_t byteInRow) {
    uint32_t chunk = byteInRow >> 4;
    return row * 64u + ((chunk ^ ((row >> 1) & 3u)) << 4) + (byteInRow & 15u);
}
__device__ __forceinline__ uint32_t pack_hi(float f0, float f1, uint32_t& lo) {
    f16 h0 = __float2half(f0), h1 = __float2half(f1);
    f16 l0 = __float2half(f0 - __half2float(h0));
    f16 l1 = __float2half(f1 - __half2float(h1));
    __half2 hh = __halves2half2(h0, h1);
    __half2 ll = __halves2half2(l0, l1);
    lo = *(uint32_t*)&ll;
    return *(uint32_t*)&hh;
}

// ---------------- templated chunk MMA ----------------------------------------
template<int NPROD>
__device__ __forceinline__ void mma_chunk(uint32_t aBase, uint32_t aLo,
                                          uint32_t bBase, uint32_t bLo,
                                          int lane, int m0w, int n0w, float acc[2][4][4])
{
    #pragma unroll
    for (int s = 0; s < 2; ++s) {
        uint32_t ah[2][4], al[2][4], bh[2][4], bl[2][4];
        #pragma unroll
        for (int mt = 0; mt < 2; ++mt) {
            const uint32_t off = swz((uint32_t)(m0w + mt * 16 + (lane & 15)),
                                     (uint32_t)(s * 32 + ((lane & 16) ? 16 : 0)));
            ldm4(ah[mt], aBase + off);
            if (NPROD == 3) ldm4(al[mt], aLo + off);
        }
        #pragma unroll
        for (int nt = 0; nt < 2; ++nt) {
            const uint32_t off = swz((uint32_t)(n0w + nt * 16 + (lane & 7) + ((lane & 16) ? 8 : 0)),
                                     (uint32_t)(s * 32 + ((lane & 8) ? 16 : 0)));
            ldm4(bh[nt], bBase + off);
            if (NPROD >= 2) ldm4(bl[nt], bLo + off);
        }
        #pragma unroll
        for (int mt = 0; mt < 2; ++mt)
            #pragma unroll
            for (int nb = 0; nb < 4; ++nb) {
                const uint32_t b0h = bh[nb >> 1][(nb & 1) * 2];
                const uint32_t b1h = bh[nb >> 1][(nb & 1) * 2 + 1];
                mma16816(acc[mt][nb], ah[mt], b0h, b1h);
                if (NPROD >= 2)
                    mma16816(acc[mt][nb], ah[mt],
                             bl[nb >> 1][(nb & 1) * 2], bl[nb >> 1][(nb & 1) * 2 + 1]);
                if (NPROD == 3)
                    mma16816(acc[mt][nb], al[mt], b0h, b1h);
            }
    }
}

// ---------------- templated pipelined GEMM ------------------------------------
template<int MW, int NPROD>
__device__ __forceinline__ void gemm_run(
    const f16* __restrict__ Ah, const f16* __restrict__ Al,
    const f16* __restrict__ Bh, const f16* __restrict__ Bl,
    float acc[2][4][4])
{
    constexpr int MTILE  = 32 * MW;
    constexpr int NTHR   = 128 * MW;
    constexpr int ATILEB = MTILE * 64;
    constexpr int NA = (NPROD == 3) ? 2 : 1;
    constexpr int NB = (NPROD >= 2) ? 2 : 1;
    constexpr uint32_t STG = (uint32_t)(NA * ATILEB + NB * BT);

    extern __shared__ char sm[];
    const uint32_t smb = smem_u32(sm);
    const int tid = threadIdx.x, lane = tid & 31, wid = tid >> 5;
    const int m0w = (wid % MW) * 32, n0w = (wid / MW) * 32;
    const int lr = tid >> 2, cc = tid & 3;
    const uint32_t sdr = swz((uint32_t)lr, (uint32_t)cc * 16u);

    #pragma unroll
    for (int mt = 0; mt < 2; ++mt)
        #pragma unroll
        for (int nb = 0; nb < 4; ++nb)
            #pragma unroll
            for (int q = 0; q < 4; ++q) acc[mt][nb][q] = 0.0f;

    auto issue = [&](int c) {
        const uint32_t st = smb + (uint32_t)(c & (DEPTH - 1)) * STG;
        {
            const size_t go = (size_t)lr * DIM + c * 32 + cc * 8;
            cp16(st + sdr, Ah + go);
            if (NPROD == 3) cp16(st + sdr + ATILEB, Al + go);
        }
        #pragma unroll
        for (int rr = 0; rr < 128; rr += NTHR / 4) {
            const int r = lr + rr;
            const uint32_t sd = st + (uint32_t)(NA * ATILEB) + swz((uint32_t)r, (uint32_t)cc * 16u);
            const size_t go = (size_t)r * DIM + c * 32 + cc * 8;
            cp16(sd, Bh + go);
            if (NPROD >= 2) cp16(sd + BT, Bl + go);
        }
    };

    #pragma unroll
    for (int p = 0; p < DEPTH - 1; ++p) { issue(p); cp_commit(); }

    for (int c = 0; c < 8; ++c) {
        cp_wait<DEPTH - 2>();
        __syncthreads();
        if (c + DEPTH - 1 < 8) issue(c + DEPTH - 1);
        cp_commit();
        const uint32_t st = smb + (uint32_t)(c & (DEPTH - 1)) * STG;
        mma_chunk<NPROD>(st, st + ATILEB, st + NA * ATILEB, st + NA * ATILEB + BT,
                         lane, m0w, n0w, acc);
    }
}

// ---------------- templated staged epilogue -----------------------------------
template<int MW>
__device__ __forceinline__ void epi_split(float acc[2][4][4], float alpha, int addI,
                                          int mo, int no,
                                          f16* __restrict__ oAh, f16* __restrict__ oAl,
                                          f16* __restrict__ oBh, f16* __restrict__ oBl)
{
    extern __shared__ char sm[];
    float* sf = (float*)sm;
    const int tid = threadIdx.x, lane = tid & 31, wid = tid >> 5;
    const int m0w = (wid % MW) * 32, n0w = (wid / MW) * 32;
    const int r0 = lane >> 2, cq = (lane & 3) * 2;

    __syncthreads();
    #pragma unroll
    for (int mt = 0; mt < 2; ++mt)
        #pragma unroll
        for (int half = 0; half < 2; ++half) {
            const int row = m0w + mt * 16 + r0 + half * 8;
            const int gr = mo + row;
            #pragma unroll
            for (int nb = 0; nb < 4; ++nb) {
                const int col = n0w + nb * 8 + cq;
                const int gc = no + col;
                float v0 = alpha * acc[mt][nb][half * 2 + 0];
                float v1 = alpha * acc[mt][nb][half * 2 + 1];
                if (addI) {
                    if (gr == gc)     v0 += 1.0f;
                    if (gr == gc + 1) v1 += 1.0f;
                }
                sf[row * PITCH + col]     = v0;
                sf[row * PITCH + col + 1] = v1;
            }
        }
    __syncthreads();

    if (oAh) {
        const int r = tid >> 2, c0 = (tid & 3) * 32;
        uint32_t hv[16], lv[16];
        #pragma unroll
        for (int j = 0; j < 16; ++j)
            hv[j] = pack_hi(sf[r * PITCH + c0 + 2*j], sf[r * PITCH + c0 + 2*j + 1], lv[j]);
        uint4* dh = (uint4*)(oAh + (size_t)(mo + r) * DIM + no + c0);
        #pragma unroll
        for (int q = 0; q < 4; ++q)
            dh[q] = make_uint4(hv[4*q], hv[4*q+1], hv[4*q+2], hv[4*q+3]);
        if (oAl) {
            uint4* dl = (uint4*)(oAl + (size_t)(mo + r) * DIM + no + c0);
            #pragma unroll
            for (int q = 0; q < 4; ++q)
                dl[q] = make_uint4(lv[4*q], lv[4*q+1], lv[4*q+2], lv[4*q+3]);
        }
    }
    {
        const int c = tid & 127, rg = tid >> 7;
        const int rb = rg * 32;
        uint32_t hv[16], lv[16];
        #pragma unroll
        for (int j = 0; j < 16; ++j)
            hv[j] = pack_hi(sf[(rb + 2*j) * PITCH + c], sf[(rb + 2*j + 1) * PITCH + c], lv[j]);
        uint4* dh = (uint4*)(oBh + (size_t)(no + c) * DIM + mo + rb);
        #pragma unroll
        for (int q = 0; q < 4; ++q)
            dh[q] = make_uint4(hv[4*q], hv[4*q+1], hv[4*q+2], hv[4*q+3]);
        if (oBl) {
            uint4* dl = (uint4*)(oBl + (size_t)(no + c) * DIM + mo + rb);
            #pragma unroll
            for (int q = 0; q < 4; ++q)
                dl[q] = make_uint4(lv[4*q], lv[4*q+1], lv[4*q+2], lv[4*q+3]);
        }
    }
    __syncthreads();
}

// ---------------- kernels -----------------------------------------------------
// A = skew^T / 16 ; seed T = I + A/4 (Taylor d=4, s=4 squarings)
__global__ void k_skew(const float* __restrict__ prim, f16* TBh, f16* TBl)
{
    int idx = blockIdx.x * blockDim.x + threadIdx.x;
    if (idx >= 2 * MATSZ) return;
    int b = idx >> 16, ij = idx & 65535, i = ij >> 8, j = ij & 255;
    float a = (prim[(size_t)b * MATSZ + (size_t)j * DIM + i] -
               prim[(size_t)b * MATSZ + (size_t)i * DIM + j]) * 0.0625f;
    f16 h = __float2half(a);
    g_eAh[idx] = h;
    g_eAl[idx] = __float2half(a - __half2float(h));
    float d = (i == j) ? 1.0f : 0.0f;
    float tb = d - a * 0.25f;          // (I + A/4)^T
    f16 th = __float2half(tb);
    TBh[idx] = th;
    TBl[idx] = __float2half(tb - __half2float(th));
}

// expm round: MW=1, NPROD=3. grid (2, 8, 2), block 128.
__global__ __launch_bounds__(128, 1)
void k_gemm_split(const f16* Ah, const f16* Al, const f16* Bh, const f16* Bl,
                  f16* oAh, f16* oAl, f16* oBh, f16* oBl, float alpha, int addI)
{
    const size_t off = (size_t)blockIdx.z * MATSZ;
    const int mo = blockIdx.y * 32, no = blockIdx.x * 128;
    float acc[2][4][4];
    gemm_run<1, 3>(Ah + off + (size_t)mo * DIM, Al + off + (size_t)mo * DIM,
                   Bh + off + (size_t)no * DIM, Bl + off + (size_t)no * DIM, acc);
    epi_split<1>(acc, alpha, addI, mo, no,
                 oAh ? oAh + off : nullptr, oAl ? oAl + off : nullptr,
                 oBh + off, oBl ? oBl + off : nullptr);
}

// table level build: MW=2, NPROD=2 (A hi only, B = parent split). block 256.
__global__ __launch_bounds__(256, 2)
void k_tab(int lvl)
{
    const int c = blockIdx.z;
    const int lb = lvl - 1;
    const size_t aoff = (size_t)(((1 << lb) - 2) + (c & ((1 << lb) - 1))) * MATSZ;
    const size_t boff = (size_t)(c >> lb) * MATSZ;
    const size_t ooff = (size_t)(((1 << lvl) - 2) + c) * MATSZ;
    const int mo = blockIdx.y * 64, no = blockIdx.x * 128;
    float acc[2][4][4];
    gemm_run<2, 2>(g_tabAh + aoff + (size_t)mo * DIM, nullptr,
                   g_tabBh + boff + (size_t)no * DIM,
                   g_tabBl + boff + (size_t)no * DIM, acc);
    epi_split<2>(acc, 1.0f, 0, mo, no,
                 g_tabAh + ooff, nullptr, g_tabBh + ooff, nullptr);
}

// ---------------- persistent leaf kernel (1-product, DEPTH=LDEPTH) ------------
__global__ __launch_bounds__(512, 1)
void k_leaf(const int* __restrict__ unique, float* __restrict__ out)
{
    extern __shared__ char sm[];
    const uint32_t smb = smem_u32(sm);
    uint4* metaM = (uint4*)(sm + LDEPTH * 16384);
    uint4* metaC = metaM + 60;
    __shared__ int cntM, cntC;
    const int tid = threadIdx.x, lane = tid & 31, wid = tid >> 5;
    const int m0w = (wid & 3) * 32, n0w = (wid >> 2) * 32;
    const int bid = blockIdx.x;

    if (tid == 0) { cntM = 0; cntC = 0; }
    __syncthreads();

    {
        const int w = bid + tid * PGRID;
        if (w < NITEMS) {
            const int n = w >> 2, tile = w & 3;
            const unsigned p = (unsigned)unique[n];
            const int len = 31 - __clz((int)p);
            if (len >= 9) {
                const uint32_t aIdx = 254u + (p & 255u);
                const int hb = len - 8;
                const uint32_t bIdx = ((1u << hb) - 2u) + ((p >> 8) & ((1u << hb) - 1u));
                const int s = atomicAdd(&cntM, 1);
                metaM[s] = make_uint4(aIdx, bIdx, (uint32_t)((n << 2) | tile), 0);
            } else {
                const uint32_t sIdx = (len >= 1)
                    ? (((1u << len) - 2u) + (p & ((1u << len) - 1u))) : 0xFFFFFFFFu;
                const int s = atomicAdd(&cntC, 1);
                metaC[s] = make_uint4(sIdx, 0, (uint32_t)((n << 2) | tile), 0);
            }
        }
    }
    __syncthreads();

    // copy / identity items
    for (int i = 0; i < cntC; ++i) {
        const uint4 mt4 = metaC[i];
        const int n = (int)(mt4.z >> 2), tile = (int)(mt4.z & 3);
        const int mo = (tile >> 1) * 128, no = (tile & 1) * 128;
        float* C = out + (size_t)n * MATSZ;
        const int r = tid >> 2, cb = (tid & 3) * 32;
        float* d = C + (size_t)(mo + r) * DIM + no + cb;
        if (mt4.x != 0xFFFFFFFFu) {
            const f16* sh = g_tabAh + (size_t)mt4.x * MATSZ + (size_t)(mo + r) * DIM + no + cb;
            #pragma unroll
            for (int j = 0; j < 16; ++j) {
                __half2 h = *(const __half2*)(sh + 2*j);
                *(float2*)(d + 2*j) = make_float2(__half2float(h.x), __half2float(h.y));
            }
        } else {
            #pragma unroll
            for (int j = 0; j < 32; ++j)
                d[j] = ((mo + r) == (no + cb + j)) ? 1.0f : 0.0f;
        }
    }

    const int G = cntM * 8;
    if (G == 0) return;
    const int lr = tid >> 2, cc = tid & 3;
    const uint32_t sd0 = swz((uint32_t)lr, (uint32_t)cc * 16u);
    const size_t rowOffA = (size_t)lr * DIM + cc * 8;

    auto issue = [&](int g) {
        const uint4 mt4 = metaM[g >> 3];
        const int c = g & 7, tile = (int)(mt4.z & 3);
        const int mo = (tile >> 1) * 128, no = (tile & 1) * 128;
        const uint32_t st = smb + (uint32_t)(g & (LDEPTH - 1)) * 16384u;
        const size_t ao = (size_t)mt4.x * MATSZ + (size_t)mo * DIM + rowOffA + c * 32;
        const size_t bo = (size_t)mt4.y * MATSZ + (size_t)no * DIM + rowOffA + c * 32;
        cp16(st + sd0,        g_tabAh + ao);
        cp16(st + sd0 + 8192, g_tabBh + bo);
    };

    float acc[2][4][4];
    #pragma unroll
    for (int mt = 0; mt < 2; ++mt)
        #pragma unroll
        for (int nb = 0; nb < 4; ++nb)
            #pragma unroll
            for (int q = 0; q < 4; ++q) acc[mt][nb][q] = 0.0f;

    #pragma unroll
    for (int p = 0; p < LDEPTH - 1; ++p) {
        if (p < G) issue(p);
        cp_commit();
    }

    for (int g = 0; g < G; ++g) {
        cp_wait<LDEPTH - 2>();
        __syncthreads();
        if (g + LDEPTH - 1 < G) issue(g + LDEPTH - 1);
        cp_commit();
        const uint32_t st = smb + (uint32_t)(g & (LDEPTH - 1)) * 16384u;
        mma_chunk<1>(st, 0, st + 8192, 0, lane, m0w, n0w, acc);

        if ((g & 7) == 7) {
            const uint4 mt4 = metaM[g >> 3];
            const int n = (int)(mt4.z >> 2), tile = (int)(mt4.z & 3);
            const int mo = (tile >> 1) * 128, no = (tile & 1) * 128;
            float* C = out + (size_t)n * MATSZ;
            const int r0 = lane >> 2, cq = (lane & 3) * 2;
            #pragma unroll
            for (int mt = 0; mt < 2; ++mt)
                #pragma unroll
                for (int half = 0; half < 2; ++half) {
                    const int gr = mo + m0w + mt * 16 + r0 + half * 8;
                    #pragma unroll
                    for (int nb = 0; nb < 4; ++nb) {
                        const int gc = no + n0w + nb * 8 + cq;
                        *(float2*)(C + (size_t)gr * DIM + gc) =
                            make_float2(acc[mt][nb][half * 2], acc[mt][nb][half * 2 + 1]);
                        acc[mt][nb][half * 2] = 0.0f;
                        acc[mt][nb][half * 2 + 1] = 0.0f;
                    }
                }
        }
    }
}

// ---------------- host orchestration -----------------------------------------
extern "C" void kernel_launch(void* const* d_in, const int* in_sizes, int n_in,
                              void* d_out, int out_size)
{
    const float* prim   = (const float*)d_in[0];
    const int*   unique = (const int*)d_in[2];
    float*       out    = (float*)d_out;
    (void)in_sizes; (void)n_in; (void)out_size;

    cudaFuncSetAttribute(k_gemm_split, cudaFuncAttributeMaxDynamicSharedMemorySize, SM_EXPM);
    cudaFuncSetAttribute(k_tab,  cudaFuncAttributeMaxDynamicSharedMemorySize, SM_TAB2);
    cudaFuncSetAttribute(k_leaf, cudaFuncAttributeMaxDynamicSharedMemorySize, SM_LEAF);

    f16 *eAh, *eAl, *TAh, *TAl, *TBh, *TBl, *tAh, *tBh, *tBl;
    cudaGetSymbolAddress((void**)&eAh, g_eAh);
    cudaGetSymbolAddress((void**)&eAl, g_eAl);
    cudaGetSymbolAddress((void**)&TAh, g_TAh);
    cudaGetSymbolAddress((void**)&TAl, g_TAl);
    cudaGetSymbolAddress((void**)&TBh, g_TBh);
    cudaGetSymbolAddress((void**)&TBl, g_TBl);
    cudaGetSymbolAddress((void**)&tAh, g_tabAh);
    cudaGetSymbolAddress((void**)&tBh, g_tabBh);
    cudaGetSymbolAddress((void**)&tBl, g_tabBl);

    auto TA_h = [&](int i) { return TAh + (size_t)i * 2 * MATSZ; };
    auto TA_l = [&](int i) { return TAl + (size_t)i * 2 * MATSZ; };
    auto TB_h = [&](int i) { return TBh + (size_t)i * 2 * MATSZ; };
    auto TB_l = [&](int i) { return TBl + (size_t)i * 2 * MATSZ; };

    const dim3 gE(2, 8, 2);

    k_skew<<<(2 * MATSZ + 255) / 256, 256>>>(prim, TB_h(0), TB_l(0));

    // Horner k=3..1 (Taylor degree 4)
    int cur = 0;
    for (int k = 3; k >= 1; --k) {
        const int nxt = cur ^ 1;
        const bool last = (k == 1);
        k_gemm_split<<<gE, 128, SM_EXPM>>>(
            eAh, eAl, TB_h(cur), TB_l(cur),
            last ? TA_h(nxt) : nullptr, last ? TA_l(nxt) : nullptr,
            TB_h(nxt), TB_l(nxt), 1.0f / (float)k, 1);
        cur = nxt;
    }
    // 4 squarings; last lands in table level-1 slots
    for (int sq = 0; sq < 4; ++sq) {
        const int nxt = cur ^ 1;
        const bool last = (sq == 3);
        k_gemm_split<<<gE, 128, SM_EXPM>>>(
            TA_h(cur), TA_l(cur), TB_h(cur), TB_l(cur),
            last ? tAh : TA_h(nxt), last ? nullptr : TA_l(nxt),
            last ? tBh : TB_h(nxt), last ? tBl : TB_l(nxt), 1.0f, 0);
        cur = nxt;
    }

    for (int lvl = 2; lvl <= 8; ++lvl)
        k_tab<<<dim3(2, 4, 1 << lvl), 256, SM_TAB2>>>(lvl);

    k_leaf<<<PGRID, 512, SM_LEAF>>>(unique, out);
}